// round 1
// baseline (speedup 1.0000x reference)
#include <cuda_runtime.h>
#include <cstddef>

#define B_   2048
#define NIN  64
#define D_   128
#define RANK 24
#define KFM  1536   // NIN*RANK
#define HID  1024
#define N3   4096   // N_FMB*D

// ---- scratch (static device globals; no runtime allocation) ----
__device__ float g_fmn[B_ * KFM];   // normalized FM features (B,1536)
__device__ float g_h1 [B_ * HID];
__device__ float g_h2 [B_ * HID];
__device__ float g_fmb[B_ * N3];    // (B, 32*128)

// ============================================================================
// Kernel 1: per-batch FM block.
//   r[d,j]  = sum_n x[b,n,d] * w_rank[n,j]        (128 x 24, K=64)
//   fm[n,j] = sum_d x[b,n,d] * r[d,j]             (64 x 24, K=128)
//   custom LN over the 1536 values (no affine, clipped std) -> g_fmn[b]
// One CTA per batch element, 256 threads.
// ============================================================================
__global__ __launch_bounds__(256) void k_fm(const float* __restrict__ x,
                                            const float* __restrict__ wr)
{
    __shared__ float xs[NIN * D_];     // 32 KB
    __shared__ float rs[D_ * RANK];    // 12 KB
    __shared__ float rsum[8], rsq[8], stats[2];

    const int b = blockIdx.x, tid = threadIdx.x;

    // load x[b] (8192 floats) as float4
    {
        const float4* xg = (const float4*)(x + (size_t)b * NIN * D_);
        float4* xs4 = (float4*)xs;
        #pragma unroll
        for (int i = 0; i < 8; i++) xs4[tid + i * 256] = xg[tid + i * 256];
    }
    __syncthreads();

    // r[d][j]: 3072 outputs, 12 per thread
    #pragma unroll
    for (int k = 0; k < 12; k++) {
        int idx = tid + k * 256;
        int d = idx / RANK;
        int j = idx - d * RANK;
        float acc = 0.f;
        #pragma unroll 8
        for (int n = 0; n < NIN; n++)
            acc += xs[n * D_ + d] * __ldg(&wr[n * RANK + j]);
        rs[d * RANK + j] = acc;
    }
    __syncthreads();

    // fm[n][j]: 1536 outputs, 6 per thread; accumulate moments
    float vals[6];
    float lsum = 0.f, lsq = 0.f;
    #pragma unroll
    for (int k = 0; k < 6; k++) {
        int idx = tid + k * 256;
        int n = idx / RANK;
        int j = idx - n * RANK;
        float acc = 0.f;
        #pragma unroll 8
        for (int d = 0; d < D_; d++)
            acc += xs[n * D_ + d] * rs[d * RANK + j];
        vals[k] = acc;
        lsum += acc;
        lsq  += acc * acc;
    }

    // block reduction for mean / var
    #pragma unroll
    for (int o = 16; o > 0; o >>= 1) {
        lsum += __shfl_xor_sync(0xFFFFFFFFu, lsum, o);
        lsq  += __shfl_xor_sync(0xFFFFFFFFu, lsq,  o);
    }
    int w = tid >> 5, lane = tid & 31;
    if (lane == 0) { rsum[w] = lsum; rsq[w] = lsq; }
    __syncthreads();
    if (tid == 0) {
        float s = 0.f, q = 0.f;
        #pragma unroll
        for (int i = 0; i < 8; i++) { s += rsum[i]; q += rsq[i]; }
        float mu  = s * (1.f / KFM);
        float var = q * (1.f / KFM) - mu * mu;
        float sd  = sqrtf(fmaxf(var, 0.f));
        sd = fminf(fmaxf(sd, 1e-11f), 1e7f);
        stats[0] = mu;
        stats[1] = 1.f / sd;
    }
    __syncthreads();
    float mu = stats[0], inv = stats[1];

    float* o = g_fmn + (size_t)b * KFM;
    #pragma unroll
    for (int k = 0; k < 6; k++)
        o[tid + k * 256] = (vals[k] - mu) * inv;
}

// ============================================================================
// Tiled fp32 GEMM: C[M,N] = (relu?)(A[M,K] @ W[K,N])
// BM=BN=128, BK=8, 8x8 per thread, 256 threads. M=2048 fixed by grid.
// ============================================================================
template <bool RELU>
__global__ __launch_bounds__(256) void k_gemm(const float* __restrict__ A,
                                              const float* __restrict__ W,
                                              float* __restrict__ C,
                                              int K, int N)
{
    __shared__ float As[8][128];
    __shared__ float Bs[8][128];

    const int tid  = threadIdx.x;
    const int brow = blockIdx.y * 128;
    const int bcol = blockIdx.x * 128;

    const int arow = tid >> 1;
    const int acol = (tid & 1) * 4;
    const int brl  = tid >> 5;
    const int bcl  = (tid & 31) * 4;
    const int ty   = tid >> 4;
    const int tx   = tid & 15;

    float acc[8][8];
    #pragma unroll
    for (int i = 0; i < 8; i++)
        #pragma unroll
        for (int j = 0; j < 8; j++) acc[i][j] = 0.f;

    const float* Ap = A + (size_t)(brow + arow) * K + acol;
    const float* Bp = W + (size_t)brl * N + bcol + bcl;

    for (int k0 = 0; k0 < K; k0 += 8) {
        float4 a4 = *(const float4*)(Ap + k0);
        float4 b4 = *(const float4*)(Bp + (size_t)k0 * N);
        As[acol + 0][arow] = a4.x;
        As[acol + 1][arow] = a4.y;
        As[acol + 2][arow] = a4.z;
        As[acol + 3][arow] = a4.w;
        *(float4*)&Bs[brl][bcl] = b4;
        __syncthreads();

        #pragma unroll
        for (int kk = 0; kk < 8; kk++) {
            float ar[8], br[8];
            *(float4*)(ar)     = *(const float4*)&As[kk][ty * 8];
            *(float4*)(ar + 4) = *(const float4*)&As[kk][ty * 8 + 4];
            *(float4*)(br)     = *(const float4*)&Bs[kk][tx * 8];
            *(float4*)(br + 4) = *(const float4*)&Bs[kk][tx * 8 + 4];
            #pragma unroll
            for (int i = 0; i < 8; i++)
                #pragma unroll
                for (int j = 0; j < 8; j++)
                    acc[i][j] += ar[i] * br[j];
        }
        __syncthreads();
    }

    #pragma unroll
    for (int i = 0; i < 8; i++) {
        int r = brow + ty * 8 + i;
        float* Cp = C + (size_t)r * N + bcol + tx * 8;
        float4 v0 = make_float4(acc[i][0], acc[i][1], acc[i][2], acc[i][3]);
        float4 v1 = make_float4(acc[i][4], acc[i][5], acc[i][6], acc[i][7]);
        if (RELU) {
            v0.x = fmaxf(v0.x, 0.f); v0.y = fmaxf(v0.y, 0.f);
            v0.z = fmaxf(v0.z, 0.f); v0.w = fmaxf(v0.w, 0.f);
            v1.x = fmaxf(v1.x, 0.f); v1.y = fmaxf(v1.y, 0.f);
            v1.z = fmaxf(v1.z, 0.f); v1.w = fmaxf(v1.w, 0.f);
        }
        *(float4*)Cp       = v0;
        *(float4*)(Cp + 4) = v1;
    }
}

// ============================================================================
// Kernel 5: epilogue. One CTA per batch element, 256 threads (8 warps).
//   row n<32 : out_row = fmb[b,n,:]
//   row n>=32: out_row = lcb[b,n-32,:] = sum_nn x[b,nn,:] * w_lcb[nn,n-32]
//   pre = out_row + x[b,n,:]            (the 1e-10*extra term is < 4e-9: dropped)
//   keras LN(axis=-1, eps=1e-3) * gamma + beta
// ============================================================================
__global__ __launch_bounds__(256) void k_epi(const float* __restrict__ x,
                                             const float* __restrict__ wl,
                                             const float* __restrict__ gamma,
                                             const float* __restrict__ beta,
                                             float* __restrict__ out)
{
    __shared__ float xs [NIN * D_];   // 32 KB
    __shared__ float wls[NIN * 32];   // 8 KB

    const int b = blockIdx.x, tid = threadIdx.x;

    {
        const float4* xg = (const float4*)(x + (size_t)b * NIN * D_);
        float4* xs4 = (float4*)xs;
        #pragma unroll
        for (int i = 0; i < 8; i++) xs4[tid + i * 256] = xg[tid + i * 256];
        const float4* wg = (const float4*)wl;
        float4* ws4 = (float4*)wls;
        #pragma unroll
        for (int i = 0; i < 2; i++) ws4[tid + i * 256] = wg[tid + i * 256];
    }
    __syncthreads();

    const int w = tid >> 5, lane = tid & 31;
    const int d0 = lane * 4;
    const float4 g4 = __ldg((const float4*)gamma + lane);
    const float4 bt = __ldg((const float4*)beta  + lane);

    #pragma unroll
    for (int rr = 0; rr < 8; rr++) {
        const int n = w + rr * 8;   // warps 0..7 -> rows n, n+8, ... (uniform branch per warp)
        float4 v;
        if (n < 32) {
            v = *(const float4*)(g_fmb + (size_t)b * N3 + n * D_ + d0);
        } else {
            const int m = n - 32;
            v = make_float4(0.f, 0.f, 0.f, 0.f);
            #pragma unroll 8
            for (int nn = 0; nn < NIN; nn++) {
                float wv  = wls[nn * 32 + m];
                float4 xv = *(const float4*)&xs[nn * D_ + d0];
                v.x += xv.x * wv; v.y += xv.y * wv;
                v.z += xv.z * wv; v.w += xv.w * wv;
            }
        }
        float4 xr = *(const float4*)&xs[n * D_ + d0];
        float4 p = make_float4(v.x + xr.x, v.y + xr.y, v.z + xr.z, v.w + xr.w);

        float s = p.x + p.y + p.z + p.w;
        float q = p.x * p.x + p.y * p.y + p.z * p.z + p.w * p.w;
        #pragma unroll
        for (int o = 16; o > 0; o >>= 1) {
            s += __shfl_xor_sync(0xFFFFFFFFu, s, o);
            q += __shfl_xor_sync(0xFFFFFFFFu, q, o);
        }
        float mean = s * (1.f / 128.f);
        float var  = q * (1.f / 128.f) - mean * mean;
        float inv  = rsqrtf(var + 1e-3f);

        float4 o4;
        o4.x = (p.x - mean) * inv * g4.x + bt.x;
        o4.y = (p.y - mean) * inv * g4.y + bt.y;
        o4.z = (p.z - mean) * inv * g4.z + bt.z;
        o4.w = (p.w - mean) * inv * g4.w + bt.w;
        *(float4*)(out + (size_t)b * NIN * D_ + n * D_ + d0) = o4;
    }
}

// ============================================================================
extern "C" void kernel_launch(void* const* d_in, const int* in_sizes, int n_in,
                              void* d_out, int out_size)
{
    const float* x      = (const float*)d_in[0];
    // d_in[1] = noise: contributes only via 1e-10*extra -> numerically irrelevant
    const float* w_lcb  = (const float*)d_in[2];
    const float* w_rank = (const float*)d_in[3];
    const float* w1     = (const float*)d_in[4];
    const float* w2     = (const float*)d_in[5];
    const float* w3     = (const float*)d_in[6];
    const float* gamma  = (const float*)d_in[7];
    const float* beta   = (const float*)d_in[8];
    float* out = (float*)d_out;

    float *fmn, *h1, *h2, *fmb;
    cudaGetSymbolAddress((void**)&fmn, g_fmn);
    cudaGetSymbolAddress((void**)&h1,  g_h1);
    cudaGetSymbolAddress((void**)&h2,  g_h2);
    cudaGetSymbolAddress((void**)&fmb, g_fmb);

    k_fm<<<B_, 256>>>(x, w_rank);
    k_gemm<true ><<<dim3(HID / 128, B_ / 128), 256>>>(fmn, w1, h1, KFM, HID);
    k_gemm<true ><<<dim3(HID / 128, B_ / 128), 256>>>(h1,  w2, h2, HID, HID);
    k_gemm<false><<<dim3(N3  / 128, B_ / 128), 256>>>(h2,  w3, fmb, HID, N3);
    k_epi<<<B_, 256>>>(x, w_lcb, gamma, beta, out);
}

// round 3
// speedup vs baseline: 2.3005x; 2.3005x over previous
#include <cuda_runtime.h>
#include <cstdint>
#include <cstddef>

#define B_   2048
#define NIN  64
#define D_   128
#define RANK 24
#define KFM  1536   // NIN*RANK
#define HID  1024
#define N3   4096   // N_FMB*D

// ---- scratch (static device globals; no runtime allocation) ----
__device__ float g_fmn[B_ * KFM];      // normalized FM features (B,1536)
__device__ float g_h1 [B_ * HID];      // relu(fmn@w1)
__device__ float g_h2 [B_ * HID];      // relu(h1@w2)
__device__ float g_fmb[B_ * N3];       // h2@w3 (B, 32*128)

// ============================================================================
// Kernel 1: per-batch FM block.
//   r[d,j]  = sum_n x[b,n,d] * w_rank[n,j]   (128 x 24, K=64)
//   fm[n,j] = sum_d x[b,n,d] * r[d,j]        (64 x 24, K=128)
//   custom LN over 1536 (no affine, clipped std) -> g_fmn[b]
// ============================================================================
__global__ __launch_bounds__(256) void k_fm(const float* __restrict__ x,
                                            const float* __restrict__ wr)
{
    __shared__ float xs[NIN * D_];
    __shared__ float rs[D_ * RANK];
    __shared__ float rsum[8], rsq[8], stats[2];

    const int b = blockIdx.x, tid = threadIdx.x;

    {
        const float4* xg = (const float4*)(x + (size_t)b * NIN * D_);
        float4* xs4 = (float4*)xs;
        #pragma unroll
        for (int i = 0; i < 8; i++) xs4[tid + i * 256] = xg[tid + i * 256];
    }
    __syncthreads();

    #pragma unroll
    for (int k = 0; k < 12; k++) {
        int idx = tid + k * 256;
        int d = idx / RANK;
        int j = idx - d * RANK;
        float acc = 0.f;
        #pragma unroll 8
        for (int n = 0; n < NIN; n++)
            acc += xs[n * D_ + d] * __ldg(&wr[n * RANK + j]);
        rs[d * RANK + j] = acc;
    }
    __syncthreads();

    float vals[6];
    float lsum = 0.f, lsq = 0.f;
    #pragma unroll
    for (int k = 0; k < 6; k++) {
        int idx = tid + k * 256;
        int n = idx / RANK;
        int j = idx - n * RANK;
        float acc = 0.f;
        #pragma unroll 8
        for (int d = 0; d < D_; d++)
            acc += xs[n * D_ + d] * rs[d * RANK + j];
        vals[k] = acc;
        lsum += acc;
        lsq  += acc * acc;
    }

    #pragma unroll
    for (int o = 16; o > 0; o >>= 1) {
        lsum += __shfl_xor_sync(0xFFFFFFFFu, lsum, o);
        lsq  += __shfl_xor_sync(0xFFFFFFFFu, lsq,  o);
    }
    int w = tid >> 5, lane = tid & 31;
    if (lane == 0) { rsum[w] = lsum; rsq[w] = lsq; }
    __syncthreads();
    if (tid == 0) {
        float s = 0.f, q = 0.f;
        #pragma unroll
        for (int i = 0; i < 8; i++) { s += rsum[i]; q += rsq[i]; }
        float mu  = s * (1.f / KFM);
        float var = q * (1.f / KFM) - mu * mu;
        float sd  = sqrtf(fmaxf(var, 0.f));
        sd = fminf(fmaxf(sd, 1e-11f), 1e7f);
        stats[0] = mu;
        stats[1] = 1.f / sd;
    }
    __syncthreads();
    float mu = stats[0], inv = stats[1];

    float* o = g_fmn + (size_t)b * KFM;
    #pragma unroll
    for (int k = 0; k < 6; k++)
        o[tid + k * 256] = (vals[k] - mu) * inv;
}

// ============================================================================
// TF32 tensor-core GEMM via mma.sync (sm_80 path; works on base sm_103 target).
//   C[M,N] = (relu?)(A[M,K] @ W[K,N]),  M=2048, K%32==0, N%128==0
// 128x128x32 CTA tile, 256 thr = 8 warps, warp tile 64x32 (4x4 m16n8k8 frags),
// cp.async double-buffered SMEM. A smem [m][k] stride 36, B smem [k][n]
// stride 136 (both conflict-free for the mma fragment pattern).
// Fragments rounded with cvt.rna.tf32 (unbiased).
// ============================================================================
#define ASTR 36
#define BSTR 136
#define A_FLOATS (128 * ASTR)          // 4608
#define B_FLOATS (32 * BSTR)           // 4352
#define STAGE_FLOATS (A_FLOATS + B_FLOATS)
#define K_MM_SMEM (2 * STAGE_FLOATS * 4)   // 71680 bytes

__device__ __forceinline__ void cpasync16(uint32_t dst, const void* src) {
    asm volatile("cp.async.cg.shared.global [%0], [%1], 16;" :: "r"(dst), "l"(src));
}
__device__ __forceinline__ uint32_t smem_u32(const void* p) {
    uint32_t a;
    asm("{ .reg .u64 t; cvta.to.shared.u64 t, %1; cvt.u32.u64 %0, t; }" : "=r"(a) : "l"(p));
    return a;
}
__device__ __forceinline__ uint32_t ld_tf32(const float* p) {
    uint32_t u;
    asm("cvt.rna.tf32.f32 %0, %1;" : "=r"(u) : "f"(*p));
    return u;
}

template<bool RELU>
__global__ __launch_bounds__(256) void k_mm(const float* __restrict__ A,
                                            const float* __restrict__ W,
                                            float* __restrict__ C,
                                            int K, int N)
{
    extern __shared__ float S[];
    const int tid  = threadIdx.x;
    const int lane = tid & 31;
    const int wid  = tid >> 5;
    const int wr   = wid >> 2;          // 0..1  (64-row slab)
    const int wc   = wid & 3;           // 0..3  (32-col slab)
    const int gid  = lane >> 2;         // 0..7
    const int tig  = lane & 3;          // 0..3

    const int brow = blockIdx.y * 128;
    const int bcol = blockIdx.x * 128;

    // per-thread cp.async coordinates
    const int arow = tid >> 1;                 // 0..127 (2 vec per row of 8)
    const int ac4a = (tid & 1) * 4;            // handles 2 float4 per row pass
    const int brw  = tid >> 5;                 // 0..7 base, 4 rows per pass... (see loop)

    float acc[4][4][4];
    #pragma unroll
    for (int i = 0; i < 4; i++)
        #pragma unroll
        for (int j = 0; j < 4; j++)
            #pragma unroll
            for (int q = 0; q < 4; q++) acc[i][j][q] = 0.f;

    const int NK = K >> 5;

    // ---- stage loaders --------------------------------------------------
    // A tile: 128 rows x 32 floats = 1024 float4; 4 per thread
    //   v = tid + i*256 : row = v>>3, c4 = v&7
    // B tile: 32 rows x 128 floats = 1024 float4; row = v>>5, c4 = v&31
    auto load_stage = [&](int s, int kc) {
        float* As = S + s * STAGE_FLOATS;
        float* Bs = As + A_FLOATS;
        const float* Ag = A + (size_t)brow * K + kc * 32;
        const float* Bg = W + (size_t)(kc * 32) * N + bcol;
        #pragma unroll
        for (int i = 0; i < 4; i++) {
            int v = tid + i * 256;
            int r = v >> 3, c = (v & 7) * 4;
            cpasync16(smem_u32(As + r * ASTR + c), Ag + (size_t)r * K + c);
        }
        #pragma unroll
        for (int i = 0; i < 4; i++) {
            int v = tid + i * 256;
            int r = v >> 5, c = (v & 31) * 4;
            cpasync16(smem_u32(Bs + r * BSTR + c), Bg + (size_t)r * N + c);
        }
    };

    load_stage(0, 0);
    asm volatile("cp.async.commit_group;");

    for (int kc = 0; kc < NK; kc++) {
        const int buf = kc & 1;
        if (kc + 1 < NK) {
            load_stage(buf ^ 1, kc + 1);
            asm volatile("cp.async.commit_group;");
            asm volatile("cp.async.wait_group 1;");
        } else {
            asm volatile("cp.async.wait_group 0;");
        }
        __syncthreads();

        const float* As = S + buf * STAGE_FLOATS;
        const float* Bs = As + A_FLOATS;

        #pragma unroll
        for (int kk = 0; kk < 32; kk += 8) {
            uint32_t a[4][4], bfr[4][2];
            #pragma unroll
            for (int mt = 0; mt < 4; mt++) {
                const float* ap = As + (wr * 64 + mt * 16 + gid) * ASTR + kk + tig;
                a[mt][0] = ld_tf32(ap);
                a[mt][1] = ld_tf32(ap + 8 * ASTR);
                a[mt][2] = ld_tf32(ap + 4);
                a[mt][3] = ld_tf32(ap + 8 * ASTR + 4);
            }
            #pragma unroll
            for (int nt = 0; nt < 4; nt++) {
                const float* bp = Bs + (kk + tig) * BSTR + wc * 32 + nt * 8 + gid;
                bfr[nt][0] = ld_tf32(bp);
                bfr[nt][1] = ld_tf32(bp + 4 * BSTR);
            }
            #pragma unroll
            for (int mt = 0; mt < 4; mt++)
                #pragma unroll
                for (int nt = 0; nt < 4; nt++)
                    asm volatile(
                        "mma.sync.aligned.m16n8k8.row.col.f32.tf32.tf32.f32 "
                        "{%0,%1,%2,%3}, {%4,%5,%6,%7}, {%8,%9}, {%0,%1,%2,%3};"
                        : "+f"(acc[mt][nt][0]), "+f"(acc[mt][nt][1]),
                          "+f"(acc[mt][nt][2]), "+f"(acc[mt][nt][3])
                        : "r"(a[mt][0]), "r"(a[mt][1]), "r"(a[mt][2]), "r"(a[mt][3]),
                          "r"(bfr[nt][0]), "r"(bfr[nt][1]));
        }
        __syncthreads();
    }

    // epilogue
    #pragma unroll
    for (int mt = 0; mt < 4; mt++) {
        const int row = brow + wr * 64 + mt * 16 + gid;
        #pragma unroll
        for (int nt = 0; nt < 4; nt++) {
            const int col = bcol + wc * 32 + nt * 8 + 2 * tig;
            float2 v0 = make_float2(acc[mt][nt][0], acc[mt][nt][1]);
            float2 v1 = make_float2(acc[mt][nt][2], acc[mt][nt][3]);
            if (RELU) {
                v0.x = fmaxf(v0.x, 0.f); v0.y = fmaxf(v0.y, 0.f);
                v1.x = fmaxf(v1.x, 0.f); v1.y = fmaxf(v1.y, 0.f);
            }
            *(float2*)(C + (size_t)row * N + col)       = v0;
            *(float2*)(C + (size_t)(row + 8) * N + col) = v1;
        }
    }
    (void)arow; (void)ac4a; (void)brw;
}

// ============================================================================
// Epilogue: lcb + residual + keras LN (1e-10*extra term numerically dropped)
// ============================================================================
__global__ __launch_bounds__(256) void k_epi(const float* __restrict__ x,
                                             const float* __restrict__ wl,
                                             const float* __restrict__ gamma,
                                             const float* __restrict__ beta,
                                             float* __restrict__ out)
{
    __shared__ float xs [NIN * D_];
    __shared__ float wls[NIN * 32];

    const int b = blockIdx.x, tid = threadIdx.x;

    {
        const float4* xg = (const float4*)(x + (size_t)b * NIN * D_);
        float4* xs4 = (float4*)xs;
        #pragma unroll
        for (int i = 0; i < 8; i++) xs4[tid + i * 256] = xg[tid + i * 256];
        const float4* wg = (const float4*)wl;
        float4* ws4 = (float4*)wls;
        #pragma unroll
        for (int i = 0; i < 2; i++) ws4[tid + i * 256] = wg[tid + i * 256];
    }
    __syncthreads();

    const int w = tid >> 5, lane = tid & 31;
    const int d0 = lane * 4;
    const float4 g4 = __ldg((const float4*)gamma + lane);
    const float4 bt = __ldg((const float4*)beta  + lane);

    #pragma unroll
    for (int rr = 0; rr < 8; rr++) {
        const int n = w + rr * 8;
        float4 v;
        if (n < 32) {
            v = *(const float4*)(g_fmb + (size_t)b * N3 + n * D_ + d0);
        } else {
            const int m = n - 32;
            v = make_float4(0.f, 0.f, 0.f, 0.f);
            #pragma unroll 8
            for (int nn = 0; nn < NIN; nn++) {
                float wv  = wls[nn * 32 + m];
                float4 xv = *(const float4*)&xs[nn * D_ + d0];
                v.x += xv.x * wv; v.y += xv.y * wv;
                v.z += xv.z * wv; v.w += xv.w * wv;
            }
        }
        float4 xr = *(const float4*)&xs[n * D_ + d0];
        float4 p = make_float4(v.x + xr.x, v.y + xr.y, v.z + xr.z, v.w + xr.w);

        float s = p.x + p.y + p.z + p.w;
        float q = p.x * p.x + p.y * p.y + p.z * p.z + p.w * p.w;
        #pragma unroll
        for (int o = 16; o > 0; o >>= 1) {
            s += __shfl_xor_sync(0xFFFFFFFFu, s, o);
            q += __shfl_xor_sync(0xFFFFFFFFu, q, o);
        }
        float mean = s * (1.f / 128.f);
        float var  = q * (1.f / 128.f) - mean * mean;
        float inv  = rsqrtf(var + 1e-3f);

        float4 o4;
        o4.x = (p.x - mean) * inv * g4.x + bt.x;
        o4.y = (p.y - mean) * inv * g4.y + bt.y;
        o4.z = (p.z - mean) * inv * g4.z + bt.z;
        o4.w = (p.w - mean) * inv * g4.w + bt.w;
        *(float4*)(out + (size_t)b * NIN * D_ + n * D_ + d0) = o4;
    }
}

// ============================================================================
extern "C" void kernel_launch(void* const* d_in, const int* in_sizes, int n_in,
                              void* d_out, int out_size)
{
    const float* x      = (const float*)d_in[0];
    // d_in[1] = noise: only enters via 1e-10*extra -> numerically irrelevant
    const float* w_lcb  = (const float*)d_in[2];
    const float* w_rank = (const float*)d_in[3];
    const float* w1     = (const float*)d_in[4];
    const float* w2     = (const float*)d_in[5];
    const float* w3     = (const float*)d_in[6];
    const float* gamma  = (const float*)d_in[7];
    const float* beta   = (const float*)d_in[8];
    float* out = (float*)d_out;

    float *fmn, *h1, *h2, *fmb;
    cudaGetSymbolAddress((void**)&fmn, g_fmn);
    cudaGetSymbolAddress((void**)&h1,  g_h1);
    cudaGetSymbolAddress((void**)&h2,  g_h2);
    cudaGetSymbolAddress((void**)&fmb, g_fmb);

    cudaFuncSetAttribute(k_mm<true>,  cudaFuncAttributeMaxDynamicSharedMemorySize, K_MM_SMEM);
    cudaFuncSetAttribute(k_mm<false>, cudaFuncAttributeMaxDynamicSharedMemorySize, K_MM_SMEM);

    k_fm<<<B_, 256>>>(x, w_rank);

    k_mm<true ><<<dim3(HID / 128, B_ / 128), 256, K_MM_SMEM>>>(fmn, w1, h1,  KFM, HID);
    k_mm<true ><<<dim3(HID / 128, B_ / 128), 256, K_MM_SMEM>>>(h1,  w2, h2,  HID, HID);
    k_mm<false><<<dim3(N3  / 128, B_ / 128), 256, K_MM_SMEM>>>(h2,  w3, fmb, HID, N3);

    k_epi<<<B_, 256>>>(x, w_lcb, gamma, beta, out);
}

// round 4
// speedup vs baseline: 3.4470x; 1.4984x over previous
#include <cuda_runtime.h>
#include <cstdint>
#include <cstddef>

#define B_   2048
#define NIN  64
#define D_   128
#define RANK 24
#define KFM  1536   // NIN*RANK
#define HID  1024
#define N3   4096   // N_FMB*D

// ---- scratch (static device globals; no runtime allocation) ----
__device__ float g_fmn[B_ * KFM];      // normalized FM features (B,1536), tf32-rounded
__device__ float g_h1 [B_ * HID];      // relu(fmn@w1), tf32-rounded
__device__ float g_h2 [B_ * HID];      // relu(h1@w2), tf32-rounded
__device__ float g_fmb[B_ * N3];       // h2@w3
__device__ float g_w1t[HID * KFM];     // w1^T [N,K] tf32-rounded
__device__ float g_w2t[HID * HID];
__device__ float g_w3t[N3  * HID];

// ============================================================================
// helpers
// ============================================================================
__device__ __forceinline__ uint32_t smem_u32(const void* p) {
    uint32_t a;
    asm("{ .reg .u64 t; cvta.to.shared.u64 t, %1; cvt.u32.u64 %0, t; }" : "=r"(a) : "l"(p));
    return a;
}
__device__ __forceinline__ void cpasync16(uint32_t dst, const void* src) {
    asm volatile("cp.async.cg.shared.global [%0], [%1], 16;" :: "r"(dst), "l"(src));
}
__device__ __forceinline__ float tf32r(float x) {
    uint32_t u;
    asm("cvt.rna.tf32.f32 %0, %1;" : "=r"(u) : "f"(x));
    return __uint_as_float(u);
}
__device__ __forceinline__ void ldmx4(uint32_t addr, uint32_t& r0, uint32_t& r1,
                                      uint32_t& r2, uint32_t& r3) {
    asm volatile("ldmatrix.sync.aligned.m8n8.x4.shared.b16 {%0,%1,%2,%3}, [%4];"
                 : "=r"(r0), "=r"(r1), "=r"(r2), "=r"(r3) : "r"(addr));
}

// ============================================================================
// k_tr: Dst[N,K] = tf32(Src[K,N]^T)
// ============================================================================
__global__ __launch_bounds__(256) void k_tr(const float* __restrict__ S,
                                            float* __restrict__ Dst, int K, int N)
{
    __shared__ float t[32][33];
    const int k0 = blockIdx.y * 32, n0 = blockIdx.x * 32;
    const int tx = threadIdx.x, ty = threadIdx.y;
    #pragma unroll
    for (int i = 0; i < 4; i++)
        t[ty + i * 8][tx] = S[(size_t)(k0 + ty + i * 8) * N + n0 + tx];
    __syncthreads();
    #pragma unroll
    for (int i = 0; i < 4; i++)
        Dst[(size_t)(n0 + ty + i * 8) * K + k0 + tx] = tf32r(t[tx][ty + i * 8]);
}

// ============================================================================
// k_fm: per-batch FM block, register-blocked, bank-tuned.
//   xsT[d][n] (stride 67), r[d,j] = sum_n xT[d,n] wr[n,j],
//   fm[n,j] = sum_d xT[d,n] r[d,j], custom LN -> g_fmn (tf32-rounded)
// dynamic smem.
// ============================================================================
#define XT_STR 67
#define FM_SMEM ((128 * XT_STR + 64 * 24 + 128 * 24 + 1536 + 32) * 4)

__global__ __launch_bounds__(256) void k_fm(const float* __restrict__ x,
                                            const float* __restrict__ wr)
{
    extern __shared__ float Sf[];
    float* xsT = Sf;                          // 128*67
    float* wrs = xsT + 128 * XT_STR;          // 64*24
    float* rs  = wrs + 64 * 24;               // 128*24
    float* fms = rs + 128 * 24;               // 1536
    float* red = fms + 1536;                  // 32 (8 sum + 8 sq + 2 stats)

    const int b = blockIdx.x, tid = threadIdx.x;
    const int lane = tid & 31, warp = tid >> 5;

    // load x[b] -> xsT transposed (scalar scatter, conflict-free via stride 67)
    {
        const float4* xg = (const float4*)(x + (size_t)b * NIN * D_);
        #pragma unroll
        for (int i = 0; i < 8; i++) {
            int v = tid + i * 256;            // 2048 float4
            float4 t = xg[v];
            int n = v >> 5, d0 = (v & 31) * 4;
            xsT[(d0 + 0) * XT_STR + n] = t.x;
            xsT[(d0 + 1) * XT_STR + n] = t.y;
            xsT[(d0 + 2) * XT_STR + n] = t.z;
            xsT[(d0 + 3) * XT_STR + n] = t.w;
        }
        // wr: 1536 floats = 384 float4
        const float4* wg = (const float4*)wr;
        float4* ws = (float4*)wrs;
        ws[tid] = wg[tid];
        if (tid < 128) ws[tid + 256] = wg[tid + 256];
    }
    __syncthreads();

    // r-loop: thread owns d = tid>>1, j-half jh = tid&1 (12 j's)
    {
        const int d = tid >> 1, jh = tid & 1;
        float racc[12];
        #pragma unroll
        for (int k = 0; k < 12; k++) racc[k] = 0.f;
        const float* xrow = xsT + d * XT_STR;
        #pragma unroll 4
        for (int n = 0; n < NIN; n++) {
            float xv = xrow[n];
            const float* wrow = wrs + n * 24 + jh * 12;
            float4 w0 = *(const float4*)(wrow);
            float4 w1 = *(const float4*)(wrow + 4);
            float4 w2 = *(const float4*)(wrow + 8);
            racc[0] += xv * w0.x; racc[1] += xv * w0.y; racc[2]  += xv * w0.z; racc[3]  += xv * w0.w;
            racc[4] += xv * w1.x; racc[5] += xv * w1.y; racc[6]  += xv * w1.z; racc[7]  += xv * w1.w;
            racc[8] += xv * w2.x; racc[9] += xv * w2.y; racc[10] += xv * w2.z; racc[11] += xv * w2.w;
        }
        float* rrow = rs + d * 24 + jh * 12;
        #pragma unroll
        for (int k = 0; k < 12; k++) rrow[k] = racc[k];
    }
    __syncthreads();

    // fm-loop: ds = tid&3 owns d = 4*dd+ds; tile = tid>>2: ng = tile>>2 (4 n's), jq = tile&3 (6 j's)
    const int ds = tid & 3, tile = tid >> 2;
    const int n0 = (tile >> 2) * 4, j0 = (tile & 3) * 6;
    float facc[4][6];
    #pragma unroll
    for (int i = 0; i < 4; i++)
        #pragma unroll
        for (int j = 0; j < 6; j++) facc[i][j] = 0.f;

    #pragma unroll 4
    for (int dd = 0; dd < 32; dd++) {
        const int d = dd * 4 + ds;
        const float* xr = xsT + d * XT_STR + n0;
        float xv0 = xr[0], xv1 = xr[1], xv2 = xr[2], xv3 = xr[3];
        const float* rrow = rs + d * 24 + j0;
        float2 r0 = *(const float2*)(rrow);
        float2 r1 = *(const float2*)(rrow + 2);
        float2 r2 = *(const float2*)(rrow + 4);
        float rv[6] = {r0.x, r0.y, r1.x, r1.y, r2.x, r2.y};
        #pragma unroll
        for (int j = 0; j < 6; j++) {
            facc[0][j] += xv0 * rv[j];
            facc[1][j] += xv1 * rv[j];
            facc[2][j] += xv2 * rv[j];
            facc[3][j] += xv3 * rv[j];
        }
    }
    // reduce across ds (lanes xor 1, 2) and accumulate LN stats on ds==0
    float lsum = 0.f, lsq = 0.f;
    #pragma unroll
    for (int i = 0; i < 4; i++)
        #pragma unroll
        for (int j = 0; j < 6; j++) {
            float v = facc[i][j];
            v += __shfl_xor_sync(0xFFFFFFFFu, v, 1);
            v += __shfl_xor_sync(0xFFFFFFFFu, v, 2);
            if (ds == 0) {
                fms[(n0 + i) * 24 + j0 + j] = v;
                lsum += v;
                lsq  += v * v;
            }
        }
    #pragma unroll
    for (int o = 16; o > 0; o >>= 1) {
        lsum += __shfl_xor_sync(0xFFFFFFFFu, lsum, o);
        lsq  += __shfl_xor_sync(0xFFFFFFFFu, lsq,  o);
    }
    if (lane == 0) { red[warp] = lsum; red[8 + warp] = lsq; }
    __syncthreads();
    if (tid == 0) {
        float s = 0.f, q = 0.f;
        #pragma unroll
        for (int i = 0; i < 8; i++) { s += red[i]; q += red[8 + i]; }
        float mu  = s * (1.f / KFM);
        float var = q * (1.f / KFM) - mu * mu;
        float sd  = sqrtf(fmaxf(var, 0.f));
        sd = fminf(fmaxf(sd, 1e-11f), 1e7f);
        red[16] = mu;
        red[17] = 1.f / sd;
    }
    __syncthreads();
    const float mu = red[16], inv = red[17];

    // normalized coalesced store (384 float4)
    float* o = g_fmn + (size_t)b * KFM;
    {
        float4 v = ((const float4*)fms)[tid];
        float4 w = make_float4(tf32r((v.x - mu) * inv), tf32r((v.y - mu) * inv),
                               tf32r((v.z - mu) * inv), tf32r((v.w - mu) * inv));
        ((float4*)o)[tid] = w;
        if (tid < 128) {
            float4 v2 = ((const float4*)fms)[tid + 256];
            float4 w2 = make_float4(tf32r((v2.x - mu) * inv), tf32r((v2.y - mu) * inv),
                                    tf32r((v2.z - mu) * inv), tf32r((v2.w - mu) * inv));
            ((float4*)o)[tid + 256] = w2;
        }
    }
}

// ============================================================================
// k_mm: TF32 mma.sync GEMM with ldmatrix fragments.
//   C[M,N] = (relu?)(A[M,K] @ Wt[N,K]^T); A,Wt K-major, pre-tf32-rounded.
// 128x128x32 CTA tile, 8 warps (2x4), warp 64x32, double-buffered cp.async.
// Both smem tiles 128 rows x 36-stride.
// ============================================================================
#define MM_ASTR 36
#define MM_TILEFL (128 * MM_ASTR)       // 4608 floats per operand tile
#define MM_STGFL (2 * MM_TILEFL)        // 9216 floats per stage
#define K_MM_SMEM (2 * MM_STGFL * 4)    // 73728 B

template<bool RELU>
__global__ __launch_bounds__(256, 2) void k_mm(const float* __restrict__ A,
                                               const float* __restrict__ Wt,
                                               float* __restrict__ C,
                                               int K, int N)
{
    extern __shared__ float S[];
    const uint32_t sbase = smem_u32(S);

    const int tid  = threadIdx.x;
    const int lane = tid & 31;
    const int wid  = tid >> 5;
    const int wr   = wid >> 2;          // 0..1
    const int wc   = wid & 3;           // 0..3
    const int gid  = lane >> 2;
    const int tig  = lane & 3;

    const int brow = blockIdx.y * 128;
    const int bcol = blockIdx.x * 128;

    // ldmatrix per-lane byte addresses (within stage 0)
    uint32_t aoff[4];
    {
        const int mrow_l = (lane & 15);
        const int mcol_l = 4 * (lane >> 4);
        #pragma unroll
        for (int mt = 0; mt < 4; mt++)
            aoff[mt] = sbase + ((wr * 64 + mt * 16 + mrow_l) * MM_ASTR + mcol_l) * 4;
    }
    uint32_t boff[2];
    {
        const int nrow_l = (lane & 7) + ((lane & 16) >> 1);
        const int ncol_l = 4 * ((lane >> 3) & 1);
        #pragma unroll
        for (int p = 0; p < 2; p++)
            boff[p] = sbase + (MM_TILEFL + (wc * 32 + p * 16 + nrow_l) * MM_ASTR + ncol_l) * 4;
    }

    float acc[4][4][4];
    #pragma unroll
    for (int i = 0; i < 4; i++)
        #pragma unroll
        for (int j = 0; j < 4; j++)
            #pragma unroll
            for (int q = 0; q < 4; q++) acc[i][j][q] = 0.f;

    const int NK = K >> 5;

    auto load_stage = [&](int s, int kc) {
        const uint32_t As = sbase + s * MM_STGFL * 4;
        const uint32_t Bs = As + MM_TILEFL * 4;
        const float* Ag = A  + (size_t)brow * K + kc * 32;
        const float* Bg = Wt + (size_t)bcol * K + kc * 32;
        #pragma unroll
        for (int i = 0; i < 4; i++) {
            int v = tid + i * 256;
            int r = v >> 3, c = (v & 7) * 4;
            cpasync16(As + (r * MM_ASTR + c) * 4, Ag + (size_t)r * K + c);
            cpasync16(Bs + (r * MM_ASTR + c) * 4, Bg + (size_t)r * K + c);
        }
    };

    load_stage(0, 0);
    asm volatile("cp.async.commit_group;");

    for (int kc = 0; kc < NK; kc++) {
        const int buf = kc & 1;
        if (kc + 1 < NK) {
            load_stage(buf ^ 1, kc + 1);
            asm volatile("cp.async.commit_group;");
            asm volatile("cp.async.wait_group 1;");
        } else {
            asm volatile("cp.async.wait_group 0;");
        }
        __syncthreads();

        const uint32_t so = buf * MM_STGFL * 4;

        #pragma unroll
        for (int kk = 0; kk < 32; kk += 8) {
            uint32_t a[4][4], bf[4][2];
            #pragma unroll
            for (int mt = 0; mt < 4; mt++)
                ldmx4(aoff[mt] + so + kk * 4, a[mt][0], a[mt][1], a[mt][2], a[mt][3]);
            #pragma unroll
            for (int p = 0; p < 2; p++)
                ldmx4(boff[p] + so + kk * 4,
                      bf[2 * p][0], bf[2 * p][1], bf[2 * p + 1][0], bf[2 * p + 1][1]);
            #pragma unroll
            for (int mt = 0; mt < 4; mt++)
                #pragma unroll
                for (int nt = 0; nt < 4; nt++)
                    asm volatile(
                        "mma.sync.aligned.m16n8k8.row.col.f32.tf32.tf32.f32 "
                        "{%0,%1,%2,%3}, {%4,%5,%6,%7}, {%8,%9}, {%0,%1,%2,%3};"
                        : "+f"(acc[mt][nt][0]), "+f"(acc[mt][nt][1]),
                          "+f"(acc[mt][nt][2]), "+f"(acc[mt][nt][3])
                        : "r"(a[mt][0]), "r"(a[mt][1]), "r"(a[mt][2]), "r"(a[mt][3]),
                          "r"(bf[nt][0]), "r"(bf[nt][1]));
        }
        __syncthreads();
    }

    #pragma unroll
    for (int mt = 0; mt < 4; mt++) {
        const int row = brow + wr * 64 + mt * 16 + gid;
        #pragma unroll
        for (int nt = 0; nt < 4; nt++) {
            const int col = bcol + wc * 32 + nt * 8 + 2 * tig;
            float2 v0 = make_float2(acc[mt][nt][0], acc[mt][nt][1]);
            float2 v1 = make_float2(acc[mt][nt][2], acc[mt][nt][3]);
            if (RELU) {
                v0.x = tf32r(fmaxf(v0.x, 0.f)); v0.y = tf32r(fmaxf(v0.y, 0.f));
                v1.x = tf32r(fmaxf(v1.x, 0.f)); v1.y = tf32r(fmaxf(v1.y, 0.f));
            }
            *(float2*)(C + (size_t)row * N + col)       = v0;
            *(float2*)(C + (size_t)(row + 8) * N + col) = v1;
        }
    }
}

// ============================================================================
// k_epi: lcb (register-blocked) + residual + keras LN.
// warp w: lcb rows 32+4w..32+4w+3, fmb rows 4w..4w+3.
// ============================================================================
__global__ __launch_bounds__(256) void k_epi(const float* __restrict__ x,
                                             const float* __restrict__ wl,
                                             const float* __restrict__ gamma,
                                             const float* __restrict__ beta,
                                             float* __restrict__ out)
{
    __shared__ float xs [NIN * D_];   // 32 KB
    __shared__ float wls[NIN * 32];   // 8 KB

    const int b = blockIdx.x, tid = threadIdx.x;
    const int w = tid >> 5, lane = tid & 31;

    {
        const float4* xg = (const float4*)(x + (size_t)b * NIN * D_);
        float4* xs4 = (float4*)xs;
        #pragma unroll
        for (int i = 0; i < 8; i++) xs4[tid + i * 256] = xg[tid + i * 256];
        const float4* wg = (const float4*)wl;
        float4* ws4 = (float4*)wls;
        #pragma unroll
        for (int i = 0; i < 2; i++) ws4[tid + i * 256] = wg[tid + i * 256];
    }
    __syncthreads();

    const float4 g4 = __ldg((const float4*)gamma + lane);
    const float4 bt = __ldg((const float4*)beta  + lane);
    const float4* xs4 = (const float4*)xs;

    // lcb: 4 m-rows per warp, register-blocked over nn
    float4 acc[4];
    #pragma unroll
    for (int i = 0; i < 4; i++) acc[i] = make_float4(0.f, 0.f, 0.f, 0.f);

    #pragma unroll 8
    for (int nn = 0; nn < NIN; nn++) {
        float4 xv = xs4[nn * 32 + lane];
        float4 w4 = *(const float4*)&wls[nn * 32 + w * 4];
        acc[0].x += xv.x * w4.x; acc[0].y += xv.y * w4.x; acc[0].z += xv.z * w4.x; acc[0].w += xv.w * w4.x;
        acc[1].x += xv.x * w4.y; acc[1].y += xv.y * w4.y; acc[1].z += xv.z * w4.y; acc[1].w += xv.w * w4.y;
        acc[2].x += xv.x * w4.z; acc[2].y += xv.y * w4.z; acc[2].z += xv.z * w4.z; acc[2].w += xv.w * w4.z;
        acc[3].x += xv.x * w4.w; acc[3].y += xv.y * w4.w; acc[3].z += xv.z * w4.w; acc[3].w += xv.w * w4.w;
    }

    float* ob = out + (size_t)b * NIN * D_;

    // 4 lcb rows (out rows 32+4w+i) then 4 fmb rows (out rows 4w+i)
    #pragma unroll
    for (int i = 0; i < 8; i++) {
        const int r = (i < 4) ? (32 + w * 4 + i) : (w * 4 + (i - 4));
        float4 v;
        if (i < 4) {
            v = acc[i];
        } else {
            v = *(const float4*)(g_fmb + (size_t)b * N3 + (r) * D_ + lane * 4);
        }
        float4 xr = xs4[r * 32 + lane];
        float4 p = make_float4(v.x + xr.x, v.y + xr.y, v.z + xr.z, v.w + xr.w);

        float s = p.x + p.y + p.z + p.w;
        float q = p.x * p.x + p.y * p.y + p.z * p.z + p.w * p.w;
        #pragma unroll
        for (int o = 16; o > 0; o >>= 1) {
            s += __shfl_xor_sync(0xFFFFFFFFu, s, o);
            q += __shfl_xor_sync(0xFFFFFFFFu, q, o);
        }
        float mean = s * (1.f / 128.f);
        float var  = q * (1.f / 128.f) - mean * mean;
        float inv  = rsqrtf(var + 1e-3f);

        float4 o4;
        o4.x = (p.x - mean) * inv * g4.x + bt.x;
        o4.y = (p.y - mean) * inv * g4.y + bt.y;
        o4.z = (p.z - mean) * inv * g4.z + bt.z;
        o4.w = (p.w - mean) * inv * g4.w + bt.w;
        *(float4*)(ob + r * D_ + lane * 4) = o4;
    }
}

// ============================================================================
extern "C" void kernel_launch(void* const* d_in, const int* in_sizes, int n_in,
                              void* d_out, int out_size)
{
    const float* x      = (const float*)d_in[0];
    // d_in[1] = noise: only enters via 1e-10*extra -> numerically irrelevant
    const float* w_lcb  = (const float*)d_in[2];
    const float* w_rank = (const float*)d_in[3];
    const float* w1     = (const float*)d_in[4];
    const float* w2     = (const float*)d_in[5];
    const float* w3     = (const float*)d_in[6];
    const float* gamma  = (const float*)d_in[7];
    const float* beta   = (const float*)d_in[8];
    float* out = (float*)d_out;

    float *fmn, *h1, *h2, *fmb, *w1t, *w2t, *w3t;
    cudaGetSymbolAddress((void**)&fmn, g_fmn);
    cudaGetSymbolAddress((void**)&h1,  g_h1);
    cudaGetSymbolAddress((void**)&h2,  g_h2);
    cudaGetSymbolAddress((void**)&fmb, g_fmb);
    cudaGetSymbolAddress((void**)&w1t, g_w1t);
    cudaGetSymbolAddress((void**)&w2t, g_w2t);
    cudaGetSymbolAddress((void**)&w3t, g_w3t);

    cudaFuncSetAttribute(k_mm<true>,  cudaFuncAttributeMaxDynamicSharedMemorySize, K_MM_SMEM);
    cudaFuncSetAttribute(k_mm<false>, cudaFuncAttributeMaxDynamicSharedMemorySize, K_MM_SMEM);
    cudaFuncSetAttribute(k_fm, cudaFuncAttributeMaxDynamicSharedMemorySize, FM_SMEM);

    // weight transpose + tf32 round (weights constant; recomputed: stateless)
    k_tr<<<dim3(HID / 32, KFM / 32), dim3(32, 8)>>>(w1, w1t, KFM, HID);
    k_tr<<<dim3(HID / 32, HID / 32), dim3(32, 8)>>>(w2, w2t, HID, HID);
    k_tr<<<dim3(N3  / 32, HID / 32), dim3(32, 8)>>>(w3, w3t, HID, N3);

    k_fm<<<B_, 256, FM_SMEM>>>(x, w_rank);

    k_mm<true ><<<dim3(HID / 128, B_ / 128), 256, K_MM_SMEM>>>(fmn, w1t, h1,  KFM, HID);
    k_mm<true ><<<dim3(HID / 128, B_ / 128), 256, K_MM_SMEM>>>(h1,  w2t, h2,  HID, HID);
    k_mm<false><<<dim3(N3  / 128, B_ / 128), 256, K_MM_SMEM>>>(h2,  w3t, fmb, HID, N3);

    k_epi<<<B_, 256>>>(x, w_lcb, gamma, beta, out);
}

// round 5
// speedup vs baseline: 3.8316x; 1.1116x over previous
#include <cuda_runtime.h>
#include <cstdint>
#include <cstddef>

#define B_   2048
#define NIN  64
#define D_   128
#define RANK 24
#define KFM  1536   // NIN*RANK
#define HID  1024
#define N3   4096   // N_FMB*D

// ---- scratch (static device globals; no runtime allocation) ----
__device__ float g_fmn[B_ * KFM];      // normalized FM features, tf32-rounded
__device__ float g_h1 [B_ * HID];
__device__ float g_h2 [B_ * HID];
__device__ float g_w1t[HID * KFM];     // w^T [N,K] tf32-rounded
__device__ float g_w2t[HID * HID];
__device__ float g_w3t[N3  * HID];

// ============================================================================
// helpers
// ============================================================================
__device__ __forceinline__ uint32_t smem_u32(const void* p) {
    uint32_t a;
    asm("{ .reg .u64 t; cvta.to.shared.u64 t, %1; cvt.u32.u64 %0, t; }" : "=r"(a) : "l"(p));
    return a;
}
__device__ __forceinline__ void cpasync16(uint32_t dst, const void* src) {
    asm volatile("cp.async.cg.shared.global [%0], [%1], 16;" :: "r"(dst), "l"(src));
}
__device__ __forceinline__ float tf32r(float x) {
    uint32_t u;
    asm("cvt.rna.tf32.f32 %0, %1;" : "=r"(u) : "f"(x));
    return __uint_as_float(u);
}
__device__ __forceinline__ void ldmx4(uint32_t addr, uint32_t& r0, uint32_t& r1,
                                      uint32_t& r2, uint32_t& r3) {
    asm volatile("ldmatrix.sync.aligned.m8n8.x4.shared.b16 {%0,%1,%2,%3}, [%4];"
                 : "=r"(r0), "=r"(r1), "=r"(r2), "=r"(r3) : "r"(addr));
}
#define MMA_TF32(acc, a, b)                                                     \
    asm volatile("mma.sync.aligned.m16n8k8.row.col.f32.tf32.tf32.f32 "          \
        "{%0,%1,%2,%3}, {%4,%5,%6,%7}, {%8,%9}, {%0,%1,%2,%3};"                 \
        : "+f"((acc)[0]), "+f"((acc)[1]), "+f"((acc)[2]), "+f"((acc)[3])        \
        : "r"((a)[0]), "r"((a)[1]), "r"((a)[2]), "r"((a)[3]),                   \
          "r"((b)[0]), "r"((b)[1]))

// ============================================================================
// k_tr: Dst[N,K] = tf32(Src[K,N]^T)
// ============================================================================
__global__ __launch_bounds__(256) void k_tr(const float* __restrict__ S,
                                            float* __restrict__ Dst, int K, int N)
{
    __shared__ float t[32][33];
    const int k0 = blockIdx.y * 32, n0 = blockIdx.x * 32;
    const int tx = threadIdx.x, ty = threadIdx.y;
    #pragma unroll
    for (int i = 0; i < 4; i++)
        t[ty + i * 8][tx] = S[(size_t)(k0 + ty + i * 8) * N + n0 + tx];
    __syncthreads();
    #pragma unroll
    for (int i = 0; i < 4; i++)
        Dst[(size_t)(n0 + ty + i * 8) * K + k0 + tx] = tf32r(t[tx][ty + i * 8]);
}

// ============================================================================
// k_fm: per-batch FM via Gram trick.
//   G = x @ x^T  (64x64, K=128)  -- tf32 mma, x is both operands
//   fm = G @ w_rank (64x24, K=64) -- fp32 SIMT, ms-split
//   custom LN -> g_fmn (tf32-rounded)
// ============================================================================
#define FM_XSTR 132
#define FM_GSTR 66
#define FM_SMEM ((64 * FM_XSTR + 64 * FM_GSTR + KFM + 32) * 4)

__global__ __launch_bounds__(256) void k_fm(const float* __restrict__ x,
                                            const float* __restrict__ wr)
{
    extern __shared__ float Sf[];
    float* xs  = Sf;                     // 64 x 132 (tf32-rounded x)
    float* Gs  = xs + 64 * FM_XSTR;      // 64 x 66
    float* ws  = Gs + 64 * FM_GSTR;      // 64 x 24
    float* red = ws + KFM;               // 32

    const int b = blockIdx.x, tid = threadIdx.x;
    const int lane = tid & 31, warp = tid >> 5;
    const int gid = lane >> 2, tig = lane & 3;

    // load x[b] tf32-rounded into stride-132 smem
    {
        const float4* xg = (const float4*)(x + (size_t)b * NIN * D_);
        #pragma unroll
        for (int i = 0; i < 8; i++) {
            int v = tid + i * 256;
            float4 t = xg[v];
            int n = v >> 5, d0 = (v & 31) * 4;
            float4 r = make_float4(tf32r(t.x), tf32r(t.y), tf32r(t.z), tf32r(t.w));
            *(float4*)&xs[n * FM_XSTR + d0] = r;
        }
        const float4* wg = (const float4*)wr;
        ((float4*)ws)[tid] = wg[tid];
        if (tid < 128) ((float4*)ws)[256 + tid] = wg[256 + tid];
    }
    __syncthreads();

    // ---- G = x @ x^T via mma: 8 warps = 4 (m) x 2 (n), warp tile 16x32 ----
    {
        const int wm = warp >> 1, wn = warp & 1;
        const uint32_t xb = smem_u32(xs);
        const uint32_t abase = xb + ((16 * wm + (lane & 15)) * FM_XSTR + 4 * (lane >> 4)) * 4;
        const int nrow_l = (lane & 7) + ((lane & 16) >> 1);
        const int ncol_l = 4 * ((lane >> 3) & 1);
        uint32_t bbase[2];
        #pragma unroll
        for (int p = 0; p < 2; p++)
            bbase[p] = xb + ((32 * wn + p * 16 + nrow_l) * FM_XSTR + ncol_l) * 4;

        float acc[4][4];
        #pragma unroll
        for (int i = 0; i < 4; i++)
            #pragma unroll
            for (int q = 0; q < 4; q++) acc[i][q] = 0.f;

        #pragma unroll
        for (int kk = 0; kk < 128; kk += 8) {
            uint32_t a[4], bf[4][2];
            ldmx4(abase + kk * 4, a[0], a[1], a[2], a[3]);
            #pragma unroll
            for (int p = 0; p < 2; p++)
                ldmx4(bbase[p] + kk * 4,
                      bf[2 * p][0], bf[2 * p][1], bf[2 * p + 1][0], bf[2 * p + 1][1]);
            #pragma unroll
            for (int nt = 0; nt < 4; nt++) MMA_TF32(acc[nt], a, bf[nt]);
        }
        #pragma unroll
        for (int nt = 0; nt < 4; nt++) {
            const int col = 32 * wn + nt * 8 + 2 * tig;
            *(float2*)&Gs[(16 * wm + gid) * FM_GSTR + col]     = make_float2(acc[nt][0], acc[nt][1]);
            *(float2*)&Gs[(16 * wm + 8 + gid) * FM_GSTR + col] = make_float2(acc[nt][2], acc[nt][3]);
        }
    }
    __syncthreads();

    // ---- fm = G @ w, fp32. tid: jq=bits0-1 (6 j), ms=bits2-3 (m-quarter), ng=bits4-7 (4 n) ----
    const int jq = tid & 3, ms = (tid >> 2) & 3, ng = tid >> 4;
    const int j0 = jq * 6;
    float f[4][6];
    #pragma unroll
    for (int i = 0; i < 4; i++)
        #pragma unroll
        for (int j = 0; j < 6; j++) f[i][j] = 0.f;

    #pragma unroll 4
    for (int mm = 0; mm < 16; mm++) {
        const int m = mm * 4 + ms;
        const float* wrow = ws + m * 24 + j0;
        float2 wa = *(const float2*)(wrow);
        float2 wb = *(const float2*)(wrow + 2);
        float2 wc = *(const float2*)(wrow + 4);
        float wv[6] = {wa.x, wa.y, wb.x, wb.y, wc.x, wc.y};
        #pragma unroll
        for (int i = 0; i < 4; i++) {
            float g = Gs[(4 * ng + i) * FM_GSTR + m];
            #pragma unroll
            for (int j = 0; j < 6; j++) f[i][j] += g * wv[j];
        }
    }
    // reduce over ms (lane bits 2,3) and LN stats
    float lsum = 0.f, lsq = 0.f;
    #pragma unroll
    for (int i = 0; i < 4; i++)
        #pragma unroll
        for (int j = 0; j < 6; j++) {
            float v = f[i][j];
            v += __shfl_xor_sync(0xFFFFFFFFu, v, 4);
            v += __shfl_xor_sync(0xFFFFFFFFu, v, 8);
            f[i][j] = v;
            if (ms == 0) { lsum += v; lsq += v * v; }
        }
    #pragma unroll
    for (int o = 16; o > 0; o >>= 1) {
        lsum += __shfl_xor_sync(0xFFFFFFFFu, lsum, o);
        lsq  += __shfl_xor_sync(0xFFFFFFFFu, lsq,  o);
    }
    if (lane == 0) { red[warp] = lsum; red[8 + warp] = lsq; }
    __syncthreads();
    if (tid == 0) {
        float s = 0.f, q = 0.f;
        #pragma unroll
        for (int i = 0; i < 8; i++) { s += red[i]; q += red[8 + i]; }
        float mu  = s * (1.f / KFM);
        float var = q * (1.f / KFM) - mu * mu;
        float sd  = sqrtf(fmaxf(var, 0.f));
        sd = fminf(fmaxf(sd, 1e-11f), 1e7f);
        red[16] = mu;
        red[17] = 1.f / sd;
    }
    __syncthreads();
    const float mu = red[16], inv = red[17];

    if (ms == 0) {
        float* o = g_fmn + (size_t)b * KFM;
        #pragma unroll
        for (int i = 0; i < 4; i++) {
            float* op = o + (4 * ng + i) * 24 + j0;
            #pragma unroll
            for (int j = 0; j < 6; j += 2) {
                float2 v = make_float2(tf32r((f[i][j] - mu) * inv),
                                       tf32r((f[i][j + 1] - mu) * inv));
                *(float2*)(op + j) = v;
            }
        }
    }
}

// ============================================================================
// k_mm: TF32 mma.sync GEMM (ldmatrix), C = relu(A @ Wt^T), tf32-rounded out.
// 128x128x32 CTA tile, 8 warps (2x4), double-buffered cp.async, stride 36.
// ============================================================================
#define MM_ASTR 36
#define MM_TILEFL (128 * MM_ASTR)
#define MM_STGFL (2 * MM_TILEFL)
#define K_MM_SMEM (2 * MM_STGFL * 4)    // 73728 B

struct MMCtx {
    uint32_t aoff[4];
    uint32_t boff[2];
    int wr, wc, gid, tig;
};
__device__ __forceinline__ void mm_setup(MMCtx& c, uint32_t sbase, int tid) {
    const int lane = tid & 31, wid = tid >> 5;
    c.wr = wid >> 2; c.wc = wid & 3;
    c.gid = lane >> 2; c.tig = lane & 3;
    const int mrow_l = lane & 15, mcol_l = 4 * (lane >> 4);
    #pragma unroll
    for (int mt = 0; mt < 4; mt++)
        c.aoff[mt] = sbase + ((c.wr * 64 + mt * 16 + mrow_l) * MM_ASTR + mcol_l) * 4;
    const int nrow_l = (lane & 7) + ((lane & 16) >> 1);
    const int ncol_l = 4 * ((lane >> 3) & 1);
    #pragma unroll
    for (int p = 0; p < 2; p++)
        c.boff[p] = sbase + (MM_TILEFL + (c.wc * 32 + p * 16 + nrow_l) * MM_ASTR + ncol_l) * 4;
}
__device__ __forceinline__ void mm_mainloop(const MMCtx& c, uint32_t sbase, int tid,
                                            const float* A, const float* Wt,
                                            int brow, int bcol, int K,
                                            float acc[4][4][4]) {
    auto load_stage = [&](int s, int kc) {
        const uint32_t As = sbase + s * MM_STGFL * 4;
        const uint32_t Bs = As + MM_TILEFL * 4;
        const float* Ag = A  + (size_t)brow * K + kc * 32;
        const float* Bg = Wt + (size_t)bcol * K + kc * 32;
        #pragma unroll
        for (int i = 0; i < 4; i++) {
            int v = tid + i * 256;
            int r = v >> 3, cc = (v & 7) * 4;
            cpasync16(As + (r * MM_ASTR + cc) * 4, Ag + (size_t)r * K + cc);
            cpasync16(Bs + (r * MM_ASTR + cc) * 4, Bg + (size_t)r * K + cc);
        }
    };
    const int NK = K >> 5;
    load_stage(0, 0);
    asm volatile("cp.async.commit_group;");
    for (int kc = 0; kc < NK; kc++) {
        const int buf = kc & 1;
        if (kc + 1 < NK) {
            load_stage(buf ^ 1, kc + 1);
            asm volatile("cp.async.commit_group;");
            asm volatile("cp.async.wait_group 1;");
        } else {
            asm volatile("cp.async.wait_group 0;");
        }
        __syncthreads();
        const uint32_t so = buf * MM_STGFL * 4;
        #pragma unroll
        for (int kk = 0; kk < 32; kk += 8) {
            uint32_t a[4][4], bf[4][2];
            #pragma unroll
            for (int mt = 0; mt < 4; mt++)
                ldmx4(c.aoff[mt] + so + kk * 4, a[mt][0], a[mt][1], a[mt][2], a[mt][3]);
            #pragma unroll
            for (int p = 0; p < 2; p++)
                ldmx4(c.boff[p] + so + kk * 4,
                      bf[2 * p][0], bf[2 * p][1], bf[2 * p + 1][0], bf[2 * p + 1][1]);
            #pragma unroll
            for (int mt = 0; mt < 4; mt++)
                #pragma unroll
                for (int nt = 0; nt < 4; nt++) MMA_TF32(acc[mt][nt], a[mt], bf[nt]);
        }
        __syncthreads();
    }
}

__global__ __launch_bounds__(256, 2) void k_mm_relu(const float* __restrict__ A,
                                                    const float* __restrict__ Wt,
                                                    float* __restrict__ C,
                                                    int K, int N)
{
    extern __shared__ float S[];
    const uint32_t sbase = smem_u32(S);
    const int tid = threadIdx.x;
    const int brow = blockIdx.y * 128, bcol = blockIdx.x * 128;
    MMCtx c; mm_setup(c, sbase, tid);
    float acc[4][4][4];
    #pragma unroll
    for (int i = 0; i < 4; i++)
        #pragma unroll
        for (int j = 0; j < 4; j++)
            #pragma unroll
            for (int q = 0; q < 4; q++) acc[i][j][q] = 0.f;
    mm_mainloop(c, sbase, tid, A, Wt, brow, bcol, K, acc);
    #pragma unroll
    for (int mt = 0; mt < 4; mt++) {
        const int row = brow + c.wr * 64 + mt * 16 + c.gid;
        #pragma unroll
        for (int nt = 0; nt < 4; nt++) {
            const int col = bcol + c.wc * 32 + nt * 8 + 2 * c.tig;
            float2 v0 = make_float2(tf32r(fmaxf(acc[mt][nt][0], 0.f)),
                                    tf32r(fmaxf(acc[mt][nt][1], 0.f)));
            float2 v1 = make_float2(tf32r(fmaxf(acc[mt][nt][2], 0.f)),
                                    tf32r(fmaxf(acc[mt][nt][3], 0.f)));
            *(float2*)(C + (size_t)row * N + col)       = v0;
            *(float2*)(C + (size_t)(row + 8) * N + col) = v1;
        }
    }
}

// ============================================================================
// k_mm_ln: final GEMM with fused residual + keras LN epilogue.
// CTA (bx, by): batches by*128.., out row n = bx (cols bx*128..+127 = full LN row).
// Stages acc in (reused) pipeline smem at stride 132, then per-row LN -> out.
// ============================================================================
#define LN_CSTR 132

__global__ __launch_bounds__(256, 2) void k_mm_ln(const float* __restrict__ A,
                                                  const float* __restrict__ Wt,
                                                  const float* __restrict__ x,
                                                  const float* __restrict__ gamma,
                                                  const float* __restrict__ beta,
                                                  float* __restrict__ out,
                                                  int K)
{
    extern __shared__ float S[];
    const uint32_t sbase = smem_u32(S);
    const int tid = threadIdx.x, lane = tid & 31, wid = tid >> 5;
    const int brow = blockIdx.y * 128, bcol = blockIdx.x * 128;
    MMCtx c; mm_setup(c, sbase, tid);
    float acc[4][4][4];
    #pragma unroll
    for (int i = 0; i < 4; i++)
        #pragma unroll
        for (int j = 0; j < 4; j++)
            #pragma unroll
            for (int q = 0; q < 4; q++) acc[i][j][q] = 0.f;
    mm_mainloop(c, sbase, tid, A, Wt, brow, bcol, K, acc);

    // stage acc -> smem (mainloop smem now free)
    float* Cs = S;
    #pragma unroll
    for (int mt = 0; mt < 4; mt++) {
        const int r0 = c.wr * 64 + mt * 16 + c.gid;
        #pragma unroll
        for (int nt = 0; nt < 4; nt++) {
            const int col = c.wc * 32 + nt * 8 + 2 * c.tig;
            *(float2*)&Cs[r0 * LN_CSTR + col]       = make_float2(acc[mt][nt][0], acc[mt][nt][1]);
            *(float2*)&Cs[(r0 + 8) * LN_CSTR + col] = make_float2(acc[mt][nt][2], acc[mt][nt][3]);
        }
    }
    __syncthreads();

    const float4 g4 = __ldg((const float4*)gamma + lane);
    const float4 bt = __ldg((const float4*)beta  + lane);

    #pragma unroll
    for (int rr = 0; rr < 16; rr++) {
        const int r = wid * 16 + rr;
        const int b = brow + r;
        float4 v = *(const float4*)&Cs[r * LN_CSTR + lane * 4];
        float4 xr = __ldg((const float4*)(x + (size_t)b * NIN * D_ + bcol + lane * 4));
        float4 p = make_float4(v.x + xr.x, v.y + xr.y, v.z + xr.z, v.w + xr.w);
        float s = p.x + p.y + p.z + p.w;
        float q = p.x * p.x + p.y * p.y + p.z * p.z + p.w * p.w;
        #pragma unroll
        for (int o = 16; o > 0; o >>= 1) {
            s += __shfl_xor_sync(0xFFFFFFFFu, s, o);
            q += __shfl_xor_sync(0xFFFFFFFFu, q, o);
        }
        float mean = s * (1.f / 128.f);
        float var  = q * (1.f / 128.f) - mean * mean;
        float inv  = rsqrtf(var + 1e-3f);
        float4 o4;
        o4.x = (p.x - mean) * inv * g4.x + bt.x;
        o4.y = (p.y - mean) * inv * g4.y + bt.y;
        o4.z = (p.z - mean) * inv * g4.z + bt.z;
        o4.w = (p.w - mean) * inv * g4.w + bt.w;
        *(float4*)(out + (size_t)b * NIN * D_ + bcol + lane * 4) = o4;
    }
}

// ============================================================================
// k_epi: lcb rows only (out rows 32..63) + residual + keras LN.
// ============================================================================
__global__ __launch_bounds__(256) void k_epi(const float* __restrict__ x,
                                             const float* __restrict__ wl,
                                             const float* __restrict__ gamma,
                                             const float* __restrict__ beta,
                                             float* __restrict__ out)
{
    __shared__ float xs [NIN * D_];
    __shared__ float wls[NIN * 32];

    const int b = blockIdx.x, tid = threadIdx.x;
    const int w = tid >> 5, lane = tid & 31;

    {
        const float4* xg = (const float4*)(x + (size_t)b * NIN * D_);
        float4* xs4 = (float4*)xs;
        #pragma unroll
        for (int i = 0; i < 8; i++) xs4[tid + i * 256] = xg[tid + i * 256];
        const float4* wg = (const float4*)wl;
        float4* ws4 = (float4*)wls;
        #pragma unroll
        for (int i = 0; i < 2; i++) ws4[tid + i * 256] = wg[tid + i * 256];
    }
    __syncthreads();

    const float4 g4 = __ldg((const float4*)gamma + lane);
    const float4 bt = __ldg((const float4*)beta  + lane);
    const float4* xs4 = (const float4*)xs;

    float4 acc[4];
    #pragma unroll
    for (int i = 0; i < 4; i++) acc[i] = make_float4(0.f, 0.f, 0.f, 0.f);

    #pragma unroll 8
    for (int nn = 0; nn < NIN; nn++) {
        float4 xv = xs4[nn * 32 + lane];
        float4 w4 = *(const float4*)&wls[nn * 32 + w * 4];
        acc[0].x += xv.x * w4.x; acc[0].y += xv.y * w4.x; acc[0].z += xv.z * w4.x; acc[0].w += xv.w * w4.x;
        acc[1].x += xv.x * w4.y; acc[1].y += xv.y * w4.y; acc[1].z += xv.z * w4.y; acc[1].w += xv.w * w4.y;
        acc[2].x += xv.x * w4.z; acc[2].y += xv.y * w4.z; acc[2].z += xv.z * w4.z; acc[2].w += xv.w * w4.z;
        acc[3].x += xv.x * w4.w; acc[3].y += xv.y * w4.w; acc[3].z += xv.z * w4.w; acc[3].w += xv.w * w4.w;
    }

    float* ob = out + (size_t)b * NIN * D_;
    #pragma unroll
    for (int i = 0; i < 4; i++) {
        const int r = 32 + w * 4 + i;
        float4 v = acc[i];
        float4 xr = xs4[r * 32 + lane];
        float4 p = make_float4(v.x + xr.x, v.y + xr.y, v.z + xr.z, v.w + xr.w);
        float s = p.x + p.y + p.z + p.w;
        float q = p.x * p.x + p.y * p.y + p.z * p.z + p.w * p.w;
        #pragma unroll
        for (int o = 16; o > 0; o >>= 1) {
            s += __shfl_xor_sync(0xFFFFFFFFu, s, o);
            q += __shfl_xor_sync(0xFFFFFFFFu, q, o);
        }
        float mean = s * (1.f / 128.f);
        float var  = q * (1.f / 128.f) - mean * mean;
        float inv  = rsqrtf(var + 1e-3f);
        float4 o4;
        o4.x = (p.x - mean) * inv * g4.x + bt.x;
        o4.y = (p.y - mean) * inv * g4.y + bt.y;
        o4.z = (p.z - mean) * inv * g4.z + bt.z;
        o4.w = (p.w - mean) * inv * g4.w + bt.w;
        *(float4*)(ob + r * D_ + lane * 4) = o4;
    }
}

// ============================================================================
extern "C" void kernel_launch(void* const* d_in, const int* in_sizes, int n_in,
                              void* d_out, int out_size)
{
    const float* x      = (const float*)d_in[0];
    // d_in[1] = noise: only enters via 1e-10*extra -> numerically irrelevant
    const float* w_lcb  = (const float*)d_in[2];
    const float* w_rank = (const float*)d_in[3];
    const float* w1     = (const float*)d_in[4];
    const float* w2     = (const float*)d_in[5];
    const float* w3     = (const float*)d_in[6];
    const float* gamma  = (const float*)d_in[7];
    const float* beta   = (const float*)d_in[8];
    float* out = (float*)d_out;

    float *fmn, *h1, *h2, *w1t, *w2t, *w3t;
    cudaGetSymbolAddress((void**)&fmn, g_fmn);
    cudaGetSymbolAddress((void**)&h1,  g_h1);
    cudaGetSymbolAddress((void**)&h2,  g_h2);
    cudaGetSymbolAddress((void**)&w1t, g_w1t);
    cudaGetSymbolAddress((void**)&w2t, g_w2t);
    cudaGetSymbolAddress((void**)&w3t, g_w3t);

    cudaFuncSetAttribute(k_mm_relu, cudaFuncAttributeMaxDynamicSharedMemorySize, K_MM_SMEM);
    cudaFuncSetAttribute(k_mm_ln,   cudaFuncAttributeMaxDynamicSharedMemorySize, K_MM_SMEM);
    cudaFuncSetAttribute(k_fm,      cudaFuncAttributeMaxDynamicSharedMemorySize, FM_SMEM);

    k_tr<<<dim3(HID / 32, KFM / 32), dim3(32, 8)>>>(w1, w1t, KFM, HID);
    k_tr<<<dim3(HID / 32, HID / 32), dim3(32, 8)>>>(w2, w2t, HID, HID);
    k_tr<<<dim3(N3  / 32, HID / 32), dim3(32, 8)>>>(w3, w3t, HID, N3);

    k_fm<<<B_, 256, FM_SMEM>>>(x, w_rank);

    k_mm_relu<<<dim3(HID / 128, B_ / 128), 256, K_MM_SMEM>>>(fmn, w1t, h1, KFM, HID);
    k_mm_relu<<<dim3(HID / 128, B_ / 128), 256, K_MM_SMEM>>>(h1,  w2t, h2, HID, HID);
    k_mm_ln  <<<dim3(N3  / 128, B_ / 128), 256, K_MM_SMEM>>>(h2,  w3t, x, gamma, beta, out, HID);

    k_epi<<<B_, 256>>>(x, w_lcb, gamma, beta, out);
}

// round 8
// speedup vs baseline: 5.6100x; 1.4641x over previous
#include <cuda_runtime.h>
#include <cuda_fp16.h>
#include <cstdint>
#include <cstddef>

#define B_   2048
#define NIN  64
#define D_   128
#define RANK 24
#define KFM  1536   // NIN*RANK
#define HID  1024
#define N3   4096   // N_FMB*D

// ---- scratch (static device globals; no runtime allocation) ----
__device__ __half g_fmn[B_ * KFM];     // normalized FM features (half)
__device__ __half g_h1 [B_ * HID];
__device__ __half g_h2 [B_ * HID];
__device__ __half g_w1t[HID * KFM];    // w^T [N,K] half
__device__ __half g_w2t[HID * HID];
__device__ __half g_w3t[N3  * HID];

// ============================================================================
// helpers
// ============================================================================
__device__ __forceinline__ uint32_t smem_u32(const void* p) {
    uint32_t a;
    asm("{ .reg .u64 t; cvta.to.shared.u64 t, %1; cvt.u32.u64 %0, t; }" : "=r"(a) : "l"(p));
    return a;
}
__device__ __forceinline__ void cpasync16(uint32_t dst, const void* src) {
    asm volatile("cp.async.cg.shared.global [%0], [%1], 16;" :: "r"(dst), "l"(src));
}
__device__ __forceinline__ void ldmx4(uint32_t addr, uint32_t& r0, uint32_t& r1,
                                      uint32_t& r2, uint32_t& r3) {
    asm volatile("ldmatrix.sync.aligned.m8n8.x4.shared.b16 {%0,%1,%2,%3}, [%4];"
                 : "=r"(r0), "=r"(r1), "=r"(r2), "=r"(r3) : "r"(addr));
}
// fp16 mma with fp32 accumulators: m16n8k16
#define MMA_F16(acc, a, b)                                                      \
    asm volatile("mma.sync.aligned.m16n8k16.row.col.f32.f16.f16.f32 "           \
        "{%0,%1,%2,%3}, {%4,%5,%6,%7}, {%8,%9}, {%0,%1,%2,%3};"                 \
        : "+f"((acc)[0]), "+f"((acc)[1]), "+f"((acc)[2]), "+f"((acc)[3])        \
        : "r"((a)[0]), "r"((a)[1]), "r"((a)[2]), "r"((a)[3]),                   \
          "r"((b)[0]), "r"((b)[1]))

// ============================================================================
// k_tr: Dst[N,K] = half(Src[K,N]^T).  32x32 tiles, block (16,16).
// ============================================================================
__global__ __launch_bounds__(256) void k_tr(const float* __restrict__ S,
                                            __half* __restrict__ Dst, int K, int N)
{
    __shared__ float t[32][33];
    const int k0 = blockIdx.y * 32, n0 = blockIdx.x * 32;
    const int tx = threadIdx.x, ty = threadIdx.y;   // 16 x 16
    #pragma unroll
    for (int i = 0; i < 2; i++) {
        float2 v = *(const float2*)&S[(size_t)(k0 + ty + i * 16) * N + n0 + 2 * tx];
        t[ty + i * 16][2 * tx]     = v.x;
        t[ty + i * 16][2 * tx + 1] = v.y;
    }
    __syncthreads();
    #pragma unroll
    for (int i = 0; i < 2; i++) {
        const int n = n0 + ty + i * 16;
        __half2 h = __floats2half2_rn(t[2 * tx][ty + i * 16], t[2 * tx + 1][ty + i * 16]);
        *(__half2*)&Dst[(size_t)n * K + k0 + 2 * tx] = h;
    }
}

// ============================================================================
// k_fm: per-batch FM (Gram trick, fp16 mma) + fused lcb/residual/LN rows 32-63.
//   G = x @ x^T  (64x64, K=128)  -- fp16 m16n8k16, x is both operands
//   fm = G @ w_rank (fp32 SIMT) -> custom LN -> g_fmn (half)
//   lcb rows + residual + keras LN -> out rows 32..63
// ============================================================================
#define FM_XF_STR 132
#define FM_XH_STR 136
#define FM_GSTR   66
// float-offset layout
#define FM_OFF_G   (64 * FM_XF_STR)                  // 8448
#define FM_OFF_WR  (FM_OFF_G + 64 * FM_GSTR)         // 12672
#define FM_OFF_WL  (FM_OFF_WR + KFM)                 // 14208
#define FM_OFF_RED (FM_OFF_WL + 2048)                // 16256
#define FM_OFF_XH  (FM_OFF_RED + 32)                 // 16288 (halves start here)
#define FM_SMEM    ((FM_OFF_XH * 4) + 64 * FM_XH_STR * 2)   // 82560 B

__global__ __launch_bounds__(256) void k_fm(const float* __restrict__ x,
                                            const float* __restrict__ wr,
                                            const float* __restrict__ wl,
                                            const float* __restrict__ gamma,
                                            const float* __restrict__ beta,
                                            float* __restrict__ out)
{
    extern __shared__ float Sf[];
    float*  xs_f = Sf;                    // 64 x 132 fp32
    float*  Gs   = Sf + FM_OFF_G;         // 64 x 66
    float*  ws   = Sf + FM_OFF_WR;        // 64 x 24
    float*  wls  = Sf + FM_OFF_WL;        // 64 x 32
    float*  red  = Sf + FM_OFF_RED;       // 32
    __half* xs_h = (__half*)(Sf + FM_OFF_XH);   // 64 x 136 half

    const int b = blockIdx.x, tid = threadIdx.x;
    const int lane = tid & 31, warp = tid >> 5;
    const int gid = lane >> 2, tig = lane & 3;

    // ---- phase 1: load x (fp32 + half copies), wr, wl ----
    {
        const float4* xg = (const float4*)(x + (size_t)b * NIN * D_);
        #pragma unroll
        for (int i = 0; i < 8; i++) {
            int v = tid + i * 256;
            float4 t = xg[v];
            int n = v >> 5, d0 = (v & 31) * 4;
            *(float4*)&xs_f[n * FM_XF_STR + d0] = t;
            *(__half2*)&xs_h[n * FM_XH_STR + d0]     = __floats2half2_rn(t.x, t.y);
            *(__half2*)&xs_h[n * FM_XH_STR + d0 + 2] = __floats2half2_rn(t.z, t.w);
        }
        const float4* wg = (const float4*)wr;
        ((float4*)ws)[tid] = wg[tid];
        if (tid < 128) ((float4*)ws)[256 + tid] = wg[256 + tid];
        const float4* wlg = (const float4*)wl;
        ((float4*)wls)[tid]       = wlg[tid];
        ((float4*)wls)[tid + 256] = wlg[tid + 256];
    }
    __syncthreads();

    // ---- phase 2: G = x @ x^T via fp16 mma (8 warps = 4m x 2n, tile 16x32) ----
    {
        const int wm = warp >> 1, wn = warp & 1;
        const uint32_t xb = smem_u32(xs_h);
        const uint32_t abase = xb + (((16 * wm + (lane & 15)) * FM_XH_STR) + (lane >> 4) * 8) * 2;
        const int nrow_l = (lane & 7) + 8 * (lane >> 4);
        const int kofs_l = ((lane >> 3) & 1) * 8;
        uint32_t bbase[2];
        #pragma unroll
        for (int p = 0; p < 2; p++)
            bbase[p] = xb + (((32 * wn + p * 16 + nrow_l) * FM_XH_STR) + kofs_l) * 2;

        float acc[4][4];
        #pragma unroll
        for (int i = 0; i < 4; i++)
            #pragma unroll
            for (int q = 0; q < 4; q++) acc[i][q] = 0.f;

        #pragma unroll
        for (int kk = 0; kk < 8; kk++) {          // 8 x k16 = 128
            const uint32_t off = kk * 32;          // 16 halves
            uint32_t a[4], bf[4][2];
            ldmx4(abase + off, a[0], a[1], a[2], a[3]);
            #pragma unroll
            for (int p = 0; p < 2; p++)
                ldmx4(bbase[p] + off,
                      bf[2 * p][0], bf[2 * p][1], bf[2 * p + 1][0], bf[2 * p + 1][1]);
            #pragma unroll
            for (int nt = 0; nt < 4; nt++) MMA_F16(acc[nt], a, bf[nt]);
        }
        #pragma unroll
        for (int nt = 0; nt < 4; nt++) {
            const int col = 32 * wn + nt * 8 + 2 * tig;
            *(float2*)&Gs[(16 * wm + gid) * FM_GSTR + col]     = make_float2(acc[nt][0], acc[nt][1]);
            *(float2*)&Gs[(16 * wm + 8 + gid) * FM_GSTR + col] = make_float2(acc[nt][2], acc[nt][3]);
        }
    }
    __syncthreads();

    // ---- phase 3: fm = G @ w (fp32, ms-split), LN, store half ----
    const int jq = tid & 3, ms = (tid >> 2) & 3, ng = tid >> 4;
    const int j0 = jq * 6;
    float f[4][6];
    #pragma unroll
    for (int i = 0; i < 4; i++)
        #pragma unroll
        for (int j = 0; j < 6; j++) f[i][j] = 0.f;

    #pragma unroll 4
    for (int mm = 0; mm < 16; mm++) {
        const int m = mm * 4 + ms;
        const float* wrow = ws + m * 24 + j0;
        float2 wa = *(const float2*)(wrow);
        float2 wb = *(const float2*)(wrow + 2);
        float2 wc = *(const float2*)(wrow + 4);
        float wv[6] = {wa.x, wa.y, wb.x, wb.y, wc.x, wc.y};
        #pragma unroll
        for (int i = 0; i < 4; i++) {
            float g = Gs[(4 * ng + i) * FM_GSTR + m];
            #pragma unroll
            for (int j = 0; j < 6; j++) f[i][j] += g * wv[j];
        }
    }
    float lsum = 0.f, lsq = 0.f;
    #pragma unroll
    for (int i = 0; i < 4; i++)
        #pragma unroll
        for (int j = 0; j < 6; j++) {
            float v = f[i][j];
            v += __shfl_xor_sync(0xFFFFFFFFu, v, 4);
            v += __shfl_xor_sync(0xFFFFFFFFu, v, 8);
            f[i][j] = v;
            if (ms == 0) { lsum += v; lsq += v * v; }
        }
    #pragma unroll
    for (int o = 16; o > 0; o >>= 1) {
        lsum += __shfl_xor_sync(0xFFFFFFFFu, lsum, o);
        lsq  += __shfl_xor_sync(0xFFFFFFFFu, lsq,  o);
    }
    if (lane == 0) { red[warp] = lsum; red[8 + warp] = lsq; }
    __syncthreads();
    if (tid == 0) {
        float s = 0.f, q = 0.f;
        #pragma unroll
        for (int i = 0; i < 8; i++) { s += red[i]; q += red[8 + i]; }
        float mu  = s * (1.f / KFM);
        float var = q * (1.f / KFM) - mu * mu;
        float sd  = sqrtf(fmaxf(var, 0.f));
        sd = fminf(fmaxf(sd, 1e-11f), 1e7f);
        red[16] = mu;
        red[17] = 1.f / sd;
    }
    __syncthreads();
    const float mu = red[16], inv = red[17];

    if (ms == 0) {
        __half* o = g_fmn + (size_t)b * KFM;
        #pragma unroll
        for (int i = 0; i < 4; i++) {
            __half* op = o + (4 * ng + i) * 24 + j0;
            #pragma unroll
            for (int j = 0; j < 6; j += 2)
                *(__half2*)(op + j) =
                    __floats2half2_rn((f[i][j] - mu) * inv, (f[i][j + 1] - mu) * inv);
        }
    }

    // ---- phase 4: fused lcb rows 32..63 + residual + keras LN ----
    {
        const float4 g4 = __ldg((const float4*)gamma + lane);
        const float4 bt = __ldg((const float4*)beta  + lane);
        const int w = warp;

        float4 acc[4];
        #pragma unroll
        for (int i = 0; i < 4; i++) acc[i] = make_float4(0.f, 0.f, 0.f, 0.f);

        #pragma unroll 8
        for (int nn = 0; nn < NIN; nn++) {
            float4 xv = *(const float4*)&xs_f[nn * FM_XF_STR + lane * 4];
            float4 w4 = *(const float4*)&wls[nn * 32 + w * 4];
            acc[0].x += xv.x * w4.x; acc[0].y += xv.y * w4.x; acc[0].z += xv.z * w4.x; acc[0].w += xv.w * w4.x;
            acc[1].x += xv.x * w4.y; acc[1].y += xv.y * w4.y; acc[1].z += xv.z * w4.y; acc[1].w += xv.w * w4.y;
            acc[2].x += xv.x * w4.z; acc[2].y += xv.y * w4.z; acc[2].z += xv.z * w4.z; acc[2].w += xv.w * w4.z;
            acc[3].x += xv.x * w4.w; acc[3].y += xv.y * w4.w; acc[3].z += xv.z * w4.w; acc[3].w += xv.w * w4.w;
        }

        float* ob = out + (size_t)b * NIN * D_;
        #pragma unroll
        for (int i = 0; i < 4; i++) {
            const int r = 32 + w * 4 + i;
            float4 v = acc[i];
            float4 xr = *(const float4*)&xs_f[r * FM_XF_STR + lane * 4];
            float4 p = make_float4(v.x + xr.x, v.y + xr.y, v.z + xr.z, v.w + xr.w);
            float s = p.x + p.y + p.z + p.w;
            float q = p.x * p.x + p.y * p.y + p.z * p.z + p.w * p.w;
            #pragma unroll
            for (int o = 16; o > 0; o >>= 1) {
                s += __shfl_xor_sync(0xFFFFFFFFu, s, o);
                q += __shfl_xor_sync(0xFFFFFFFFu, q, o);
            }
            float mean = s * (1.f / 128.f);
            float var  = q * (1.f / 128.f) - mean * mean;
            float invs = rsqrtf(var + 1e-3f);
            float4 o4;
            o4.x = (p.x - mean) * invs * g4.x + bt.x;
            o4.y = (p.y - mean) * invs * g4.y + bt.y;
            o4.z = (p.z - mean) * invs * g4.z + bt.z;
            o4.w = (p.w - mean) * invs * g4.w + bt.w;
            *(float4*)(ob + r * D_ + lane * 4) = o4;
        }
    }
}

// ============================================================================
// k_mm: fp16 mma.sync GEMM (m16n8k16), ldmatrix b16 fragments.
//   C = relu(A @ Wt^T) (half out) / fused LN variant (fp32 out).
// 128x128x64 CTA tile, 8 warps (2x4), double-buffered cp.async, stride 72 halves.
// ============================================================================
#define MM_HSTR 72
#define MM_TILEB (128 * MM_HSTR * 2)    // 18432 B per operand tile
#define MM_STGB  (2 * MM_TILEB)         // 36864 B per stage
#define K_MM_SMEM (2 * MM_STGB)         // 73728 B

struct MMCtx {
    uint32_t aoff[4];
    uint32_t boff[2];
    int wr, wc, gid, tig;
};
__device__ __forceinline__ void mm_setup(MMCtx& c, uint32_t sbase, int tid) {
    const int lane = tid & 31, wid = tid >> 5;
    c.wr = wid >> 2; c.wc = wid & 3;
    c.gid = lane >> 2; c.tig = lane & 3;
    #pragma unroll
    for (int mt = 0; mt < 4; mt++)
        c.aoff[mt] = sbase + (((c.wr * 64 + mt * 16 + (lane & 15)) * MM_HSTR) + (lane >> 4) * 8) * 2;
    const int nrow_l = (lane & 7) + 8 * (lane >> 4);
    const int kofs_l = ((lane >> 3) & 1) * 8;
    #pragma unroll
    for (int p = 0; p < 2; p++)
        c.boff[p] = sbase + MM_TILEB + (((c.wc * 32 + p * 16 + nrow_l) * MM_HSTR) + kofs_l) * 2;
}
__device__ __forceinline__ void mm_mainloop(const MMCtx& c, uint32_t sbase, int tid,
                                            const __half* A, const __half* Wt,
                                            int brow, int bcol, int K,
                                            float acc[4][4][4]) {
    auto load_stage = [&](int s, int kc) {
        const uint32_t As = sbase + s * MM_STGB;
        const uint32_t Bs = As + MM_TILEB;
        const __half* Ag = A  + (size_t)brow * K + kc * 64;
        const __half* Bg = Wt + (size_t)bcol * K + kc * 64;
        #pragma unroll
        for (int i = 0; i < 4; i++) {
            int v = tid + i * 256;
            int r = v >> 3, ch = (v & 7) * 8;         // 8-half (16B) chunks
            cpasync16(As + (r * MM_HSTR + ch) * 2, Ag + (size_t)r * K + ch);
            cpasync16(Bs + (r * MM_HSTR + ch) * 2, Bg + (size_t)r * K + ch);
        }
    };
    const int NK = K >> 6;
    load_stage(0, 0);
    asm volatile("cp.async.commit_group;");
    for (int kc = 0; kc < NK; kc++) {
        const int buf = kc & 1;
        if (kc + 1 < NK) {
            load_stage(buf ^ 1, kc + 1);
            asm volatile("cp.async.commit_group;");
            asm volatile("cp.async.wait_group 1;");
        } else {
            asm volatile("cp.async.wait_group 0;");
        }
        __syncthreads();
        const uint32_t so = buf * MM_STGB;
        #pragma unroll
        for (int kk = 0; kk < 4; kk++) {              // 4 x k16 = 64
            const uint32_t off = so + kk * 32;
            uint32_t a[4][4], bf[4][2];
            #pragma unroll
            for (int mt = 0; mt < 4; mt++)
                ldmx4(c.aoff[mt] + off, a[mt][0], a[mt][1], a[mt][2], a[mt][3]);
            #pragma unroll
            for (int p = 0; p < 2; p++)
                ldmx4(c.boff[p] + off,
                      bf[2 * p][0], bf[2 * p][1], bf[2 * p + 1][0], bf[2 * p + 1][1]);
            #pragma unroll
            for (int mt = 0; mt < 4; mt++)
                #pragma unroll
                for (int nt = 0; nt < 4; nt++) MMA_F16(acc[mt][nt], a[mt], bf[nt]);
        }
        __syncthreads();
    }
}

__global__ __launch_bounds__(256, 2) void k_mm_relu(const __half* __restrict__ A,
                                                    const __half* __restrict__ Wt,
                                                    __half* __restrict__ C,
                                                    int K, int N)
{
    extern __shared__ char smraw[];
    const uint32_t sbase = smem_u32(smraw);
    const int tid = threadIdx.x;
    const int brow = blockIdx.y * 128, bcol = blockIdx.x * 128;
    MMCtx c; mm_setup(c, sbase, tid);
    float acc[4][4][4];
    #pragma unroll
    for (int i = 0; i < 4; i++)
        #pragma unroll
        for (int j = 0; j < 4; j++)
            #pragma unroll
            for (int q = 0; q < 4; q++) acc[i][j][q] = 0.f;
    mm_mainloop(c, sbase, tid, A, Wt, brow, bcol, K, acc);
    #pragma unroll
    for (int mt = 0; mt < 4; mt++) {
        const int row = brow + c.wr * 64 + mt * 16 + c.gid;
        #pragma unroll
        for (int nt = 0; nt < 4; nt++) {
            const int col = bcol + c.wc * 32 + nt * 8 + 2 * c.tig;
            __half2 h0 = __floats2half2_rn(fmaxf(acc[mt][nt][0], 0.f), fmaxf(acc[mt][nt][1], 0.f));
            __half2 h1 = __floats2half2_rn(fmaxf(acc[mt][nt][2], 0.f), fmaxf(acc[mt][nt][3], 0.f));
            *(__half2*)(C + (size_t)row * N + col)       = h0;
            *(__half2*)(C + (size_t)(row + 8) * N + col) = h1;
        }
    }
}

#define LN_CSTR 132

__global__ __launch_bounds__(256, 2) void k_mm_ln(const __half* __restrict__ A,
                                                  const __half* __restrict__ Wt,
                                                  const float* __restrict__ x,
                                                  const float* __restrict__ gamma,
                                                  const float* __restrict__ beta,
                                                  float* __restrict__ out,
                                                  int K)
{
    extern __shared__ char smraw[];
    float* S = (float*)smraw;
    const uint32_t sbase = smem_u32(smraw);
    const int tid = threadIdx.x, lane = tid & 31, wid = tid >> 5;
    const int brow = blockIdx.y * 128, bcol = blockIdx.x * 128;
    MMCtx c; mm_setup(c, sbase, tid);
    float acc[4][4][4];
    #pragma unroll
    for (int i = 0; i < 4; i++)
        #pragma unroll
        for (int j = 0; j < 4; j++)
            #pragma unroll
            for (int q = 0; q < 4; q++) acc[i][j][q] = 0.f;
    mm_mainloop(c, sbase, tid, A, Wt, brow, bcol, K, acc);

    // stage acc -> smem (mainloop smem now free; 128*132*4 = 67584 <= 73728)
    #pragma unroll
    for (int mt = 0; mt < 4; mt++) {
        const int r0 = c.wr * 64 + mt * 16 + c.gid;
        #pragma unroll
        for (int nt = 0; nt < 4; nt++) {
            const int col = c.wc * 32 + nt * 8 + 2 * c.tig;
            *(float2*)&S[r0 * LN_CSTR + col]       = make_float2(acc[mt][nt][0], acc[mt][nt][1]);
            *(float2*)&S[(r0 + 8) * LN_CSTR + col] = make_float2(acc[mt][nt][2], acc[mt][nt][3]);
        }
    }
    __syncthreads();

    const float4 g4 = __ldg((const float4*)gamma + lane);
    const float4 bt = __ldg((const float4*)beta  + lane);

    #pragma unroll
    for (int rr = 0; rr < 16; rr++) {
        const int r = wid * 16 + rr;
        const int b = brow + r;
        float4 v = *(const float4*)&S[r * LN_CSTR + lane * 4];
        float4 xr = __ldg((const float4*)(x + (size_t)b * NIN * D_ + bcol + lane * 4));
        float4 p = make_float4(v.x + xr.x, v.y + xr.y, v.z + xr.z, v.w + xr.w);
        float s = p.x + p.y + p.z + p.w;
        float q = p.x * p.x + p.y * p.y + p.z * p.z + p.w * p.w;
        #pragma unroll
        for (int o = 16; o > 0; o >>= 1) {
            s += __shfl_xor_sync(0xFFFFFFFFu, s, o);
            q += __shfl_xor_sync(0xFFFFFFFFu, q, o);
        }
        float mean = s * (1.f / 128.f);
        float var  = q * (1.f / 128.f) - mean * mean;
        float inv  = rsqrtf(var + 1e-3f);
        float4 o4;
        o4.x = (p.x - mean) * inv * g4.x + bt.x;
        o4.y = (p.y - mean) * inv * g4.y + bt.y;
        o4.z = (p.z - mean) * inv * g4.z + bt.z;
        o4.w = (p.w - mean) * inv * g4.w + bt.w;
        *(float4*)(out + (size_t)b * NIN * D_ + bcol + lane * 4) = o4;
    }
}

// ============================================================================
extern "C" void kernel_launch(void* const* d_in, const int* in_sizes, int n_in,
                              void* d_out, int out_size)
{
    const float* x      = (const float*)d_in[0];
    // d_in[1] = noise: only enters via 1e-10*extra -> numerically irrelevant
    const float* w_lcb  = (const float*)d_in[2];
    const float* w_rank = (const float*)d_in[3];
    const float* w1     = (const float*)d_in[4];
    const float* w2     = (const float*)d_in[5];
    const float* w3     = (const float*)d_in[6];
    const float* gamma  = (const float*)d_in[7];
    const float* beta   = (const float*)d_in[8];
    float* out = (float*)d_out;

    __half *fmn, *h1, *h2, *w1t, *w2t, *w3t;
    cudaGetSymbolAddress((void**)&fmn, g_fmn);
    cudaGetSymbolAddress((void**)&h1,  g_h1);
    cudaGetSymbolAddress((void**)&h2,  g_h2);
    cudaGetSymbolAddress((void**)&w1t, g_w1t);
    cudaGetSymbolAddress((void**)&w2t, g_w2t);
    cudaGetSymbolAddress((void**)&w3t, g_w3t);

    cudaFuncSetAttribute(k_mm_relu, cudaFuncAttributeMaxDynamicSharedMemorySize, K_MM_SMEM);
    cudaFuncSetAttribute(k_mm_ln,   cudaFuncAttributeMaxDynamicSharedMemorySize, K_MM_SMEM);
    cudaFuncSetAttribute(k_fm,      cudaFuncAttributeMaxDynamicSharedMemorySize, FM_SMEM);

    // weight transpose + fp16 convert (weights constant; recomputed: stateless)
    k_tr<<<dim3(HID / 32, KFM / 32), dim3(16, 16)>>>(w1, w1t, KFM, HID);
    k_tr<<<dim3(HID / 32, HID / 32), dim3(16, 16)>>>(w2, w2t, HID, HID);
    k_tr<<<dim3(N3  / 32, HID / 32), dim3(16, 16)>>>(w3, w3t, HID, N3);

    // FM block + fused lcb/LN rows 32..63
    k_fm<<<B_, 256, FM_SMEM>>>(x, w_rank, w_lcb, gamma, beta, out);

    k_mm_relu<<<dim3(HID / 128, B_ / 128), 256, K_MM_SMEM>>>(fmn, w1t, h1, KFM, HID);
    k_mm_relu<<<dim3(HID / 128, B_ / 128), 256, K_MM_SMEM>>>(h1,  w2t, h2, HID, HID);
    k_mm_ln  <<<dim3(N3  / 128, B_ / 128), 256, K_MM_SMEM>>>(h2,  w3t, x, gamma, beta, out, HID);
}

// round 9
// speedup vs baseline: 6.5974x; 1.1760x over previous
#include <cuda_runtime.h>
#include <cuda_fp16.h>
#include <cstdint>
#include <cstddef>

#define B_   2048
#define NIN  64
#define D_   128
#define RANK 24
#define KFM  1536   // NIN*RANK
#define HID  1024
#define N3   4096   // N_FMB*D

// ---- scratch (static device globals; no runtime allocation) ----
__device__ __half g_fmn[B_ * KFM];     // normalized FM features (half)
__device__ __half g_h1 [B_ * HID];
__device__ __half g_h2 [B_ * HID];
__device__ __half g_w1t[HID * KFM];    // w^T [N,K] half
__device__ __half g_w2t[HID * HID];
__device__ __half g_w3t[N3  * HID];

// ============================================================================
// helpers
// ============================================================================
__device__ __forceinline__ uint32_t smem_u32(const void* p) {
    uint32_t a;
    asm("{ .reg .u64 t; cvta.to.shared.u64 t, %1; cvt.u32.u64 %0, t; }" : "=r"(a) : "l"(p));
    return a;
}
__device__ __forceinline__ void cpasync16(uint32_t dst, const void* src) {
    asm volatile("cp.async.cg.shared.global [%0], [%1], 16;" :: "r"(dst), "l"(src));
}
__device__ __forceinline__ void ldmx4(uint32_t addr, uint32_t& r0, uint32_t& r1,
                                      uint32_t& r2, uint32_t& r3) {
    asm volatile("ldmatrix.sync.aligned.m8n8.x4.shared.b16 {%0,%1,%2,%3}, [%4];"
                 : "=r"(r0), "=r"(r1), "=r"(r2), "=r"(r3) : "r"(addr));
}
__device__ __forceinline__ void ldmx4t(uint32_t addr, uint32_t& r0, uint32_t& r1,
                                       uint32_t& r2, uint32_t& r3) {
    asm volatile("ldmatrix.sync.aligned.m8n8.x4.trans.shared.b16 {%0,%1,%2,%3}, [%4];"
                 : "=r"(r0), "=r"(r1), "=r"(r2), "=r"(r3) : "r"(addr));
}
// fp16 mma with fp32 accumulators: m16n8k16
#define MMA_F16(acc, a, b)                                                      \
    asm volatile("mma.sync.aligned.m16n8k16.row.col.f32.f16.f16.f32 "           \
        "{%0,%1,%2,%3}, {%4,%5,%6,%7}, {%8,%9}, {%0,%1,%2,%3};"                 \
        : "+f"((acc)[0]), "+f"((acc)[1]), "+f"((acc)[2]), "+f"((acc)[3])        \
        : "r"((a)[0]), "r"((a)[1]), "r"((a)[2]), "r"((a)[3]),                   \
          "r"((b)[0]), "r"((b)[1]))

// ============================================================================
// k_tr: Dst[N,K] = half(Src[K,N]^T).  32x32 tiles, block (16,16).
// ============================================================================
__global__ __launch_bounds__(256) void k_tr(const float* __restrict__ S,
                                            __half* __restrict__ Dst, int K, int N)
{
    __shared__ float t[32][33];
    const int k0 = blockIdx.y * 32, n0 = blockIdx.x * 32;
    const int tx = threadIdx.x, ty = threadIdx.y;   // 16 x 16
    #pragma unroll
    for (int i = 0; i < 2; i++) {
        float2 v = *(const float2*)&S[(size_t)(k0 + ty + i * 16) * N + n0 + 2 * tx];
        t[ty + i * 16][2 * tx]     = v.x;
        t[ty + i * 16][2 * tx + 1] = v.y;
    }
    __syncthreads();
    #pragma unroll
    for (int i = 0; i < 2; i++) {
        const int n = n0 + ty + i * 16;
        __half2 h = __floats2half2_rn(t[2 * tx][ty + i * 16], t[2 * tx + 1][ty + i * 16]);
        *(__half2*)&Dst[(size_t)n * K + k0 + 2 * tx] = h;
    }
}

// ============================================================================
// k_fm: per-batch FM (Gram trick) + lcb both on fp16 mma; fused LN rows 32-63.
//   G   = x @ x^T        (64x64, K=128)  fp16 mma, x both operands
//   lcb = wl^T @ x       (32x128, K=64)  fp16 mma via ldmatrix.trans
//   fm  = G @ w_rank     fp32 SIMT -> custom LN -> g_fmn (half)
//   lcb + residual(global) + keras LN -> out rows 32..63
// smem (floats): Gs[4224] | ws[1536] | red[32] | xs_h 64x136 h | wl_h 64x40 h
// ============================================================================
#define FM_XH_STR 136
#define FM_GSTR   66
#define FM_OFF_WR  (64 * FM_GSTR)            // 4224
#define FM_OFF_RED (FM_OFF_WR + KFM)         // 5760
#define FM_OFF_XH  (FM_OFF_RED + 32)         // 5792 (byte 23168, 16B aligned)
#define FM_XH_BYTES (64 * FM_XH_STR * 2)     // 17408
#define FM_WL_BYTES (64 * 40 * 2)            // 5120
#define FM_SMEM (FM_OFF_XH * 4 + FM_XH_BYTES + FM_WL_BYTES)   // 45696 B

__global__ __launch_bounds__(256, 3) void k_fm(const float* __restrict__ x,
                                               const float* __restrict__ wr,
                                               const float* __restrict__ wl,
                                               const float* __restrict__ gamma,
                                               const float* __restrict__ beta,
                                               float* __restrict__ out)
{
    extern __shared__ float Sf[];
    float*  Gs   = Sf;                                   // 64 x 66
    float*  ws   = Sf + FM_OFF_WR;                       // 64 x 24
    float*  red  = Sf + FM_OFF_RED;                      // 32
    __half* xs_h = (__half*)(Sf + FM_OFF_XH);            // 64 x 136
    __half* wl_h = (__half*)((char*)(Sf + FM_OFF_XH) + FM_XH_BYTES);  // 64 x 40

    const int b = blockIdx.x, tid = threadIdx.x;
    const int lane = tid & 31, warp = tid >> 5;
    const int gid = lane >> 2, tig = lane & 3;

    // ---- phase 1: load x -> half smem; wr -> fp32; wl -> half [k][m] ----
    {
        const float4* xg = (const float4*)(x + (size_t)b * NIN * D_);
        #pragma unroll
        for (int i = 0; i < 8; i++) {
            int v = tid + i * 256;
            float4 t = xg[v];
            int n = v >> 5, d0 = (v & 31) * 4;
            *(__half2*)&xs_h[n * FM_XH_STR + d0]     = __floats2half2_rn(t.x, t.y);
            *(__half2*)&xs_h[n * FM_XH_STR + d0 + 2] = __floats2half2_rn(t.z, t.w);
        }
        const float4* wg = (const float4*)wr;
        ((float4*)ws)[tid] = wg[tid];
        if (tid < 128) ((float4*)ws)[256 + tid] = wg[256 + tid];
        // wl: [64][32] f32 = 512 float4 -> wl_h[nn*40 + m]
        const float4* wlg = (const float4*)wl;
        #pragma unroll
        for (int i = 0; i < 2; i++) {
            int idx = tid + i * 256;
            float4 t = wlg[idx];
            int nn = idx >> 3, m0 = (idx & 7) * 4;
            *(__half2*)&wl_h[nn * 40 + m0]     = __floats2half2_rn(t.x, t.y);
            *(__half2*)&wl_h[nn * 40 + m0 + 2] = __floats2half2_rn(t.z, t.w);
        }
    }
    __syncthreads();

    // ---- phase 2a: G = x @ x^T (8 warps = 4m x 2n, warp tile 16x32) ----
    const uint32_t xb = smem_u32(xs_h);
    {
        const int wm = warp >> 1, wn = warp & 1;
        const uint32_t abase = xb + (((16 * wm + (lane & 15)) * FM_XH_STR) + (lane >> 4) * 8) * 2;
        const int nrow_l = (lane & 7) + 8 * (lane >> 4);
        const int kofs_l = ((lane >> 3) & 1) * 8;
        uint32_t bbase[2];
        #pragma unroll
        for (int p = 0; p < 2; p++)
            bbase[p] = xb + (((32 * wn + p * 16 + nrow_l) * FM_XH_STR) + kofs_l) * 2;

        float acc[4][4];
        #pragma unroll
        for (int i = 0; i < 4; i++)
            #pragma unroll
            for (int q = 0; q < 4; q++) acc[i][q] = 0.f;

        #pragma unroll
        for (int kk = 0; kk < 8; kk++) {
            const uint32_t off = kk * 32;
            uint32_t a[4], bf[4][2];
            ldmx4(abase + off, a[0], a[1], a[2], a[3]);
            #pragma unroll
            for (int p = 0; p < 2; p++)
                ldmx4(bbase[p] + off,
                      bf[2 * p][0], bf[2 * p][1], bf[2 * p + 1][0], bf[2 * p + 1][1]);
            #pragma unroll
            for (int nt = 0; nt < 4; nt++) MMA_F16(acc[nt], a, bf[nt]);
        }
        #pragma unroll
        for (int nt = 0; nt < 4; nt++) {
            const int col = 32 * wn + nt * 8 + 2 * tig;
            *(float2*)&Gs[(16 * wm + gid) * FM_GSTR + col]     = make_float2(acc[nt][0], acc[nt][1]);
            *(float2*)&Gs[(16 * wm + 8 + gid) * FM_GSTR + col] = make_float2(acc[nt][2], acc[nt][3]);
        }
    }

    // ---- phase 2b: lcb = wl^T @ x (8 warps = 2m x 4n, warp tile 16x32) ----
    float lacc[4][4];
    const int wm2 = warp >> 2, wn2 = warp & 3;
    {
        #pragma unroll
        for (int i = 0; i < 4; i++)
            #pragma unroll
            for (int q = 0; q < 4; q++) lacc[i][q] = 0.f;

        const uint32_t wlb = smem_u32(wl_h);
        // A (trans from [k][m]): k_off=(l&7)+8*((l>>4)&1), m_off=8*((l>>3)&1)
        const uint32_t a_addr = wlb +
            (((lane & 7) + 8 * ((lane >> 4) & 1)) * 40 + 16 * wm2 + 8 * ((lane >> 3) & 1)) * 2;
        // B (trans from [k][n]): k_off=(l&7)+8*((l>>3)&1), n_off=8*(l>>4)
        const int kofB = (lane & 7) + 8 * ((lane >> 3) & 1);
        const int nofB = 8 * (lane >> 4);
        uint32_t b_addr[2];
        #pragma unroll
        for (int p = 0; p < 2; p++)
            b_addr[p] = xb + (kofB * FM_XH_STR + 32 * wn2 + 16 * p + nofB) * 2;

        #pragma unroll
        for (int kk = 0; kk < 4; kk++) {            // K = 64 = 4 x k16
            uint32_t a[4], bf[4][2];
            ldmx4t(a_addr + kk * 16 * 40 * 2, a[0], a[1], a[2], a[3]);
            #pragma unroll
            for (int p = 0; p < 2; p++)
                ldmx4t(b_addr[p] + kk * 16 * FM_XH_STR * 2,
                       bf[2 * p][0], bf[2 * p][1], bf[2 * p + 1][0], bf[2 * p + 1][1]);
            #pragma unroll
            for (int nt = 0; nt < 4; nt++) MMA_F16(lacc[nt], a, bf[nt]);
        }
    }
    __syncthreads();

    // ---- phase 3: fm = G @ w (fp32, ms-split), LN, store half ----
    const int jq = tid & 3, ms = (tid >> 2) & 3, ng = tid >> 4;
    const int j0 = jq * 6;
    float f[4][6];
    #pragma unroll
    for (int i = 0; i < 4; i++)
        #pragma unroll
        for (int j = 0; j < 6; j++) f[i][j] = 0.f;

    #pragma unroll 4
    for (int mm = 0; mm < 16; mm++) {
        const int m = mm * 4 + ms;
        const float* wrow = ws + m * 24 + j0;
        float2 wa = *(const float2*)(wrow);
        float2 wb = *(const float2*)(wrow + 2);
        float2 wc = *(const float2*)(wrow + 4);
        float wv[6] = {wa.x, wa.y, wb.x, wb.y, wc.x, wc.y};
        #pragma unroll
        for (int i = 0; i < 4; i++) {
            float g = Gs[(4 * ng + i) * FM_GSTR + m];
            #pragma unroll
            for (int j = 0; j < 6; j++) f[i][j] += g * wv[j];
        }
    }
    float lsum = 0.f, lsq = 0.f;
    #pragma unroll
    for (int i = 0; i < 4; i++)
        #pragma unroll
        for (int j = 0; j < 6; j++) {
            float v = f[i][j];
            v += __shfl_xor_sync(0xFFFFFFFFu, v, 4);
            v += __shfl_xor_sync(0xFFFFFFFFu, v, 8);
            f[i][j] = v;
            if (ms == 0) { lsum += v; lsq += v * v; }
        }
    #pragma unroll
    for (int o = 16; o > 0; o >>= 1) {
        lsum += __shfl_xor_sync(0xFFFFFFFFu, lsum, o);
        lsq  += __shfl_xor_sync(0xFFFFFFFFu, lsq,  o);
    }
    if (lane == 0) { red[warp] = lsum; red[8 + warp] = lsq; }
    __syncthreads();
    if (tid == 0) {
        float s = 0.f, q = 0.f;
        #pragma unroll
        for (int i = 0; i < 8; i++) { s += red[i]; q += red[8 + i]; }
        float mu  = s * (1.f / KFM);
        float var = q * (1.f / KFM) - mu * mu;
        float sd  = sqrtf(fmaxf(var, 0.f));
        sd = fminf(fmaxf(sd, 1e-11f), 1e7f);
        red[16] = mu;
        red[17] = 1.f / sd;
    }
    __syncthreads();
    const float mu = red[16], inv = red[17];

    if (ms == 0) {
        __half* o = g_fmn + (size_t)b * KFM;
        #pragma unroll
        for (int i = 0; i < 4; i++) {
            __half* op = o + (4 * ng + i) * 24 + j0;
            #pragma unroll
            for (int j = 0; j < 6; j += 2)
                *(__half2*)(op + j) =
                    __floats2half2_rn((f[i][j] - mu) * inv, (f[i][j + 1] - mu) * inv);
        }
    }

    // ---- phase 4: stage lcb into Gs (now free: 32x132 = 4224 floats), LN ----
    float* Ls = Gs;
    #pragma unroll
    for (int nt = 0; nt < 4; nt++) {
        const int col = 32 * wn2 + nt * 8 + 2 * tig;
        *(float2*)&Ls[(16 * wm2 + gid) * 132 + col]     = make_float2(lacc[nt][0], lacc[nt][1]);
        *(float2*)&Ls[(16 * wm2 + 8 + gid) * 132 + col] = make_float2(lacc[nt][2], lacc[nt][3]);
    }
    __syncthreads();

    {
        const float4 g4 = __ldg((const float4*)gamma + lane);
        const float4 bt = __ldg((const float4*)beta  + lane);
        float* ob = out + (size_t)b * NIN * D_;
        #pragma unroll
        for (int i = 0; i < 4; i++) {
            const int sr = warp * 4 + i;          // staged row 0..31
            const int r  = 32 + sr;               // out row
            float4 v  = *(const float4*)&Ls[sr * 132 + lane * 4];
            float4 xr = __ldg((const float4*)(x + (size_t)b * NIN * D_ + r * D_ + lane * 4));
            float4 p = make_float4(v.x + xr.x, v.y + xr.y, v.z + xr.z, v.w + xr.w);
            float s = p.x + p.y + p.z + p.w;
            float q = p.x * p.x + p.y * p.y + p.z * p.z + p.w * p.w;
            #pragma unroll
            for (int o = 16; o > 0; o >>= 1) {
                s += __shfl_xor_sync(0xFFFFFFFFu, s, o);
                q += __shfl_xor_sync(0xFFFFFFFFu, q, o);
            }
            float mean = s * (1.f / 128.f);
            float var  = q * (1.f / 128.f) - mean * mean;
            float invs = rsqrtf(var + 1e-3f);
            float4 o4;
            o4.x = (p.x - mean) * invs * g4.x + bt.x;
            o4.y = (p.y - mean) * invs * g4.y + bt.y;
            o4.z = (p.z - mean) * invs * g4.z + bt.z;
            o4.w = (p.w - mean) * invs * g4.w + bt.w;
            *(float4*)(ob + r * D_ + lane * 4) = o4;
        }
    }
}

// ============================================================================
// k_mm: fp16 mma.sync GEMM (m16n8k16), ldmatrix b16 fragments.
// 128x128x64 CTA tile, 8 warps (2x4), double-buffered cp.async, stride 72 halves.
// ============================================================================
#define MM_HSTR 72
#define MM_TILEB (128 * MM_HSTR * 2)    // 18432 B per operand tile
#define MM_STGB  (2 * MM_TILEB)         // 36864 B per stage
#define K_MM_SMEM (2 * MM_STGB)         // 73728 B

struct MMCtx {
    uint32_t aoff[4];
    uint32_t boff[2];
    int wr, wc, gid, tig;
};
__device__ __forceinline__ void mm_setup(MMCtx& c, uint32_t sbase, int tid) {
    const int lane = tid & 31, wid = tid >> 5;
    c.wr = wid >> 2; c.wc = wid & 3;
    c.gid = lane >> 2; c.tig = lane & 3;
    #pragma unroll
    for (int mt = 0; mt < 4; mt++)
        c.aoff[mt] = sbase + (((c.wr * 64 + mt * 16 + (lane & 15)) * MM_HSTR) + (lane >> 4) * 8) * 2;
    const int nrow_l = (lane & 7) + 8 * (lane >> 4);
    const int kofs_l = ((lane >> 3) & 1) * 8;
    #pragma unroll
    for (int p = 0; p < 2; p++)
        c.boff[p] = sbase + MM_TILEB + (((c.wc * 32 + p * 16 + nrow_l) * MM_HSTR) + kofs_l) * 2;
}
__device__ __forceinline__ void mm_mainloop(const MMCtx& c, uint32_t sbase, int tid,
                                            const __half* A, const __half* Wt,
                                            int brow, int bcol, int K,
                                            float acc[4][4][4]) {
    auto load_stage = [&](int s, int kc) {
        const uint32_t As = sbase + s * MM_STGB;
        const uint32_t Bs = As + MM_TILEB;
        const __half* Ag = A  + (size_t)brow * K + kc * 64;
        const __half* Bg = Wt + (size_t)bcol * K + kc * 64;
        #pragma unroll
        for (int i = 0; i < 4; i++) {
            int v = tid + i * 256;
            int r = v >> 3, ch = (v & 7) * 8;
            cpasync16(As + (r * MM_HSTR + ch) * 2, Ag + (size_t)r * K + ch);
            cpasync16(Bs + (r * MM_HSTR + ch) * 2, Bg + (size_t)r * K + ch);
        }
    };
    const int NK = K >> 6;
    load_stage(0, 0);
    asm volatile("cp.async.commit_group;");
    for (int kc = 0; kc < NK; kc++) {
        const int buf = kc & 1;
        if (kc + 1 < NK) {
            load_stage(buf ^ 1, kc + 1);
            asm volatile("cp.async.commit_group;");
            asm volatile("cp.async.wait_group 1;");
        } else {
            asm volatile("cp.async.wait_group 0;");
        }
        __syncthreads();
        const uint32_t so = buf * MM_STGB;
        #pragma unroll
        for (int kk = 0; kk < 4; kk++) {
            const uint32_t off = so + kk * 32;
            uint32_t a[4][4], bf[4][2];
            #pragma unroll
            for (int mt = 0; mt < 4; mt++)
                ldmx4(c.aoff[mt] + off, a[mt][0], a[mt][1], a[mt][2], a[mt][3]);
            #pragma unroll
            for (int p = 0; p < 2; p++)
                ldmx4(c.boff[p] + off,
                      bf[2 * p][0], bf[2 * p][1], bf[2 * p + 1][0], bf[2 * p + 1][1]);
            #pragma unroll
            for (int mt = 0; mt < 4; mt++)
                #pragma unroll
                for (int nt = 0; nt < 4; nt++) MMA_F16(acc[mt][nt], a[mt], bf[nt]);
        }
        __syncthreads();
    }
}

__global__ __launch_bounds__(256, 2) void k_mm_relu(const __half* __restrict__ A,
                                                    const __half* __restrict__ Wt,
                                                    __half* __restrict__ C,
                                                    int K, int N)
{
    extern __shared__ char smraw[];
    const uint32_t sbase = smem_u32(smraw);
    const int tid = threadIdx.x;
    const int brow = blockIdx.y * 128, bcol = blockIdx.x * 128;
    MMCtx c; mm_setup(c, sbase, tid);
    float acc[4][4][4];
    #pragma unroll
    for (int i = 0; i < 4; i++)
        #pragma unroll
        for (int j = 0; j < 4; j++)
            #pragma unroll
            for (int q = 0; q < 4; q++) acc[i][j][q] = 0.f;
    mm_mainloop(c, sbase, tid, A, Wt, brow, bcol, K, acc);
    #pragma unroll
    for (int mt = 0; mt < 4; mt++) {
        const int row = brow + c.wr * 64 + mt * 16 + c.gid;
        #pragma unroll
        for (int nt = 0; nt < 4; nt++) {
            const int col = bcol + c.wc * 32 + nt * 8 + 2 * c.tig;
            __half2 h0 = __floats2half2_rn(fmaxf(acc[mt][nt][0], 0.f), fmaxf(acc[mt][nt][1], 0.f));
            __half2 h1 = __floats2half2_rn(fmaxf(acc[mt][nt][2], 0.f), fmaxf(acc[mt][nt][3], 0.f));
            *(__half2*)(C + (size_t)row * N + col)       = h0;
            *(__half2*)(C + (size_t)(row + 8) * N + col) = h1;
        }
    }
}

#define LN_CSTR 132

__global__ __launch_bounds__(256, 2) void k_mm_ln(const __half* __restrict__ A,
                                                  const __half* __restrict__ Wt,
                                                  const float* __restrict__ x,
                                                  const float* __restrict__ gamma,
                                                  const float* __restrict__ beta,
                                                  float* __restrict__ out,
                                                  int K)
{
    extern __shared__ char smraw[];
    float* S = (float*)smraw;
    const uint32_t sbase = smem_u32(smraw);
    const int tid = threadIdx.x, lane = tid & 31, wid = tid >> 5;
    const int brow = blockIdx.y * 128, bcol = blockIdx.x * 128;
    MMCtx c; mm_setup(c, sbase, tid);
    float acc[4][4][4];
    #pragma unroll
    for (int i = 0; i < 4; i++)
        #pragma unroll
        for (int j = 0; j < 4; j++)
            #pragma unroll
            for (int q = 0; q < 4; q++) acc[i][j][q] = 0.f;
    mm_mainloop(c, sbase, tid, A, Wt, brow, bcol, K, acc);

    #pragma unroll
    for (int mt = 0; mt < 4; mt++) {
        const int r0 = c.wr * 64 + mt * 16 + c.gid;
        #pragma unroll
        for (int nt = 0; nt < 4; nt++) {
            const int col = c.wc * 32 + nt * 8 + 2 * c.tig;
            *(float2*)&S[r0 * LN_CSTR + col]       = make_float2(acc[mt][nt][0], acc[mt][nt][1]);
            *(float2*)&S[(r0 + 8) * LN_CSTR + col] = make_float2(acc[mt][nt][2], acc[mt][nt][3]);
        }
    }
    __syncthreads();

    const float4 g4 = __ldg((const float4*)gamma + lane);
    const float4 bt = __ldg((const float4*)beta  + lane);

    #pragma unroll
    for (int rr = 0; rr < 16; rr++) {
        const int r = wid * 16 + rr;
        const int b = brow + r;
        float4 v = *(const float4*)&S[r * LN_CSTR + lane * 4];
        float4 xr = __ldg((const float4*)(x + (size_t)b * NIN * D_ + bcol + lane * 4));
        float4 p = make_float4(v.x + xr.x, v.y + xr.y, v.z + xr.z, v.w + xr.w);
        float s = p.x + p.y + p.z + p.w;
        float q = p.x * p.x + p.y * p.y + p.z * p.z + p.w * p.w;
        #pragma unroll
        for (int o = 16; o > 0; o >>= 1) {
            s += __shfl_xor_sync(0xFFFFFFFFu, s, o);
            q += __shfl_xor_sync(0xFFFFFFFFu, q, o);
        }
        float mean = s * (1.f / 128.f);
        float var  = q * (1.f / 128.f) - mean * mean;
        float inv  = rsqrtf(var + 1e-3f);
        float4 o4;
        o4.x = (p.x - mean) * inv * g4.x + bt.x;
        o4.y = (p.y - mean) * inv * g4.y + bt.y;
        o4.z = (p.z - mean) * inv * g4.z + bt.z;
        o4.w = (p.w - mean) * inv * g4.w + bt.w;
        *(float4*)(out + (size_t)b * NIN * D_ + bcol + lane * 4) = o4;
    }
}

// ============================================================================
extern "C" void kernel_launch(void* const* d_in, const int* in_sizes, int n_in,
                              void* d_out, int out_size)
{
    const float* x      = (const float*)d_in[0];
    // d_in[1] = noise: only enters via 1e-10*extra -> numerically irrelevant
    const float* w_lcb  = (const float*)d_in[2];
    const float* w_rank = (const float*)d_in[3];
    const float* w1     = (const float*)d_in[4];
    const float* w2     = (const float*)d_in[5];
    const float* w3     = (const float*)d_in[6];
    const float* gamma  = (const float*)d_in[7];
    const float* beta   = (const float*)d_in[8];
    float* out = (float*)d_out;

    __half *fmn, *h1, *h2, *w1t, *w2t, *w3t;
    cudaGetSymbolAddress((void**)&fmn, g_fmn);
    cudaGetSymbolAddress((void**)&h1,  g_h1);
    cudaGetSymbolAddress((void**)&h2,  g_h2);
    cudaGetSymbolAddress((void**)&w1t, g_w1t);
    cudaGetSymbolAddress((void**)&w2t, g_w2t);
    cudaGetSymbolAddress((void**)&w3t, g_w3t);

    cudaFuncSetAttribute(k_mm_relu, cudaFuncAttributeMaxDynamicSharedMemorySize, K_MM_SMEM);
    cudaFuncSetAttribute(k_mm_ln,   cudaFuncAttributeMaxDynamicSharedMemorySize, K_MM_SMEM);
    cudaFuncSetAttribute(k_fm,      cudaFuncAttributeMaxDynamicSharedMemorySize, FM_SMEM);

    k_tr<<<dim3(HID / 32, KFM / 32), dim3(16, 16)>>>(w1, w1t, KFM, HID);
    k_tr<<<dim3(HID / 32, HID / 32), dim3(16, 16)>>>(w2, w2t, HID, HID);
    k_tr<<<dim3(N3  / 32, HID / 32), dim3(16, 16)>>>(w3, w3t, HID, N3);

    k_fm<<<B_, 256, FM_SMEM>>>(x, w_rank, w_lcb, gamma, beta, out);

    k_mm_relu<<<dim3(HID / 128, B_ / 128), 256, K_MM_SMEM>>>(fmn, w1t, h1, KFM, HID);
    k_mm_relu<<<dim3(HID / 128, B_ / 128), 256, K_MM_SMEM>>>(h1,  w2t, h2, HID, HID);
    k_mm_ln  <<<dim3(N3  / 128, B_ / 128), 256, K_MM_SMEM>>>(h2,  w3t, x, gamma, beta, out, HID);
}